// round 2
// baseline (speedup 1.0000x reference)
#include <cuda_runtime.h>
#include <math.h>

// Problem constants
#define BB   4
#define TT   2048
#define DM   1024
#define HH   16
#define HD   64
#define NF   128
#define CC   128              // chunk length
#define NCH  (TT/CC)          // 16 chunks
#define ROWS (BB*TT)          // 8192
#define BHT  (BB*HH*TT)       // 131072
#define EPSV 1e-6f
#define INV_SQRT_NF 0.08838834764831845f

// ---------------- scratch (device globals; no runtime allocation) -------------
__device__ float g_q [ROWS*DM];
__device__ float g_k [ROWS*DM];
__device__ float g_v [ROWS*DM];
__device__ float g_y [ROWS*DM];
__device__ float g_qp[(size_t)BHT*NF];
__device__ float g_kp[(size_t)BHT*NF];
__device__ float g_S [(size_t)BB*HH*NCH*NF*HD];
__device__ float g_z [(size_t)BB*HH*NCH*NF];

// ---------------- generic fp32 tiled GEMM: C[M,N] = A[M,K] @ B[K,N] ----------
#define GM 64
#define GN 64
#define GK 16
__global__ __launch_bounds__(256) void gemm_kernel(const float* __restrict__ A,
                                                   const float* __restrict__ B,
                                                   float* __restrict__ Cmat,
                                                   int M, int N, int K) {
    __shared__ float As[GK][GM + 4];
    __shared__ float Bs[GK][GN + 4];
    int tid = threadIdx.x;
    int tx = tid & 15, ty = tid >> 4;
    int bm = blockIdx.y * GM, bn = blockIdx.x * GN;

    float acc[4][4];
#pragma unroll
    for (int i = 0; i < 4; i++)
#pragma unroll
        for (int j = 0; j < 4; j++) acc[i][j] = 0.f;

    for (int k0 = 0; k0 < K; k0 += GK) {
        // A tile 64x16 (transposed into As[k][m])
        {
            int row = tid >> 2;
            int kk  = (tid & 3) * 4;
            float4 a = *(const float4*)(A + (size_t)(bm + row) * K + k0 + kk);
            As[kk + 0][row] = a.x;
            As[kk + 1][row] = a.y;
            As[kk + 2][row] = a.z;
            As[kk + 3][row] = a.w;
        }
        // B tile 16x64
        {
            int krow = tid >> 4;
            int nn   = (tid & 15) * 4;
            *(float4*)(&Bs[krow][nn]) =
                *(const float4*)(B + (size_t)(k0 + krow) * N + bn + nn);
        }
        __syncthreads();
#pragma unroll
        for (int kk = 0; kk < GK; kk++) {
            float4 a4 = *(const float4*)(&As[kk][ty * 4]);
            float4 b4 = *(const float4*)(&Bs[kk][tx * 4]);
            float a[4] = {a4.x, a4.y, a4.z, a4.w};
            float b[4] = {b4.x, b4.y, b4.z, b4.w};
#pragma unroll
            for (int i = 0; i < 4; i++)
#pragma unroll
                for (int j = 0; j < 4; j++) acc[i][j] += a[i] * b[j];
        }
        __syncthreads();
    }
#pragma unroll
    for (int i = 0; i < 4; i++) {
        float4 r = make_float4(acc[i][0], acc[i][1], acc[i][2], acc[i][3]);
        *(float4*)(Cmat + (size_t)(bm + ty * 4 + i) * N + bn + tx * 4) = r;
    }
}

// ---------------- FAVOR+ feature map -----------------------------------------
// src: (B,T,H*HD) row-major; dst: (B,H,T,NF) row-major (row index = bh*T + t)
#define FK_ROWS 16
__global__ __launch_bounds__(128) void feature_kernel(const float* __restrict__ q,
                                                      const float* __restrict__ k,
                                                      const float* __restrict__ Wf,
                                                      float* __restrict__ qp,
                                                      float* __restrict__ kp) {
    const float* src = blockIdx.y ? k : q;
    float* dst = blockIdx.y ? kp : qp;
    __shared__ float Wfs[NF * 68];      // [f][d], padded
    __shared__ float qs[FK_ROWS][68];   // padded rows
    int tid = threadIdx.x;

    // transpose W_feat (HD x NF) into Wfs[f][d]
    for (int i = tid; i < HD * NF; i += 128) {
        int d = i >> 7, f = i & 127;
        Wfs[f * 68 + d] = Wf[i];
    }
    int row0 = blockIdx.x * FK_ROWS;
    for (int i = tid; i < FK_ROWS * HD; i += 128) {
        int rr = i >> 6, d = i & 63;
        int row = row0 + rr;
        int bh = row / TT, t = row % TT;
        int b = bh >> 4, h = bh & 15;
        qs[rr][d] = src[(size_t)(b * TT + t) * DM + h * HD + d];
    }
    __syncthreads();

    const float4* wrow = (const float4*)(Wfs + tid * 68);
#pragma unroll 4
    for (int rr = 0; rr < FK_ROWS; rr++) {
        const float4* qrow = (const float4*)(&qs[rr][0]);
        float d0 = 0.f, d1 = 0.f, s0 = 0.f, s1 = 0.f;
#pragma unroll
        for (int j = 0; j < 16; j++) {
            float4 w = wrow[j];
            float4 qv = qrow[j];
            d0 += w.x * qv.x + w.y * qv.y;
            d1 += w.z * qv.z + w.w * qv.w;
            s0 += qv.x * qv.x + qv.y * qv.y;
            s1 += qv.z * qv.z + qv.w * qv.w;
        }
        float val = expf((d0 + d1) - 0.5f * (s0 + s1)) * INV_SQRT_NF;
        dst[(size_t)(row0 + rr) * NF + tid] = val;
    }
}

// ---------------- per-chunk local K^T V and sum(k) ----------------------------
__global__ __launch_bounds__(256) void chunk_kv_kernel(const float* __restrict__ kp,
                                                       const float* __restrict__ v,
                                                       float* __restrict__ Sc,
                                                       float* __restrict__ zc) {
    int blk = blockIdx.x;
    int c = blk % NCH, bh = blk / NCH;
    int b = bh / HH, h = bh % HH;
    __shared__ float kps[16 * NF];
    __shared__ float vs[16 * HD];
    int tid = threadIdx.x;
    int e0 = (tid & 15) * 4;
    int f0 = tid >> 4;   // 0..15

    float acc[8][4];
#pragma unroll
    for (int j = 0; j < 8; j++)
#pragma unroll
        for (int i = 0; i < 4; i++) acc[j][i] = 0.f;

    const float* kp_base = kp + ((size_t)bh * TT + c * CC) * NF;

    for (int tt = 0; tt < CC / 16; tt++) {
        __syncthreads();
        for (int i = tid; i < 16 * NF / 4; i += 256)
            ((float4*)kps)[i] = ((const float4*)(kp_base + tt * 16 * NF))[i];
        for (int i = tid; i < 16 * HD / 4; i += 256) {
            int t = i >> 4, e4 = i & 15;
            ((float4*)vs)[i] = *(const float4*)(
                v + (size_t)(b * TT + c * CC + tt * 16 + t) * DM + h * HD + e4 * 4);
        }
        __syncthreads();
#pragma unroll 4
        for (int t = 0; t < 16; t++) {
            float4 vv = *(const float4*)(vs + t * HD + e0);
#pragma unroll
            for (int j = 0; j < 8; j++) {
                float kf = kps[t * NF + f0 + 16 * j];
                acc[j][0] += kf * vv.x;
                acc[j][1] += kf * vv.y;
                acc[j][2] += kf * vv.z;
                acc[j][3] += kf * vv.w;
            }
        }
    }
    float* Sbase = Sc + (size_t)blk * NF * HD;
#pragma unroll
    for (int j = 0; j < 8; j++) {
        int f = f0 + 16 * j;
        *(float4*)(Sbase + f * HD + e0) =
            make_float4(acc[j][0], acc[j][1], acc[j][2], acc[j][3]);
    }
    __syncthreads();
    if (tid < NF) {
        float zz = 0.f;
        for (int t = 0; t < CC; t++) zz += kp_base[t * NF + tid];
        zc[(size_t)blk * NF + tid] = zz;
    }
}

// ---------------- exclusive prefix over chunks (per bh stream) ----------------
__global__ __launch_bounds__(256) void prefix_kernel(float* __restrict__ Sc,
                                                     float* __restrict__ zc) {
    int bh = blockIdx.x;
    int tid = threadIdx.x;
    for (int idx = tid; idx < NF * HD; idx += 256) {
        float run = 0.f;
        float* p = Sc + (size_t)bh * NCH * NF * HD + idx;
        for (int c = 0; c < NCH; c++) {
            float t = p[(size_t)c * NF * HD];
            p[(size_t)c * NF * HD] = run;
            run += t;
        }
    }
    for (int idx = tid; idx < NF; idx += 256) {
        float run = 0.f;
        float* p = zc + (size_t)bh * NCH * NF + idx;
        for (int c = 0; c < NCH; c++) {
            float t = p[c * NF];
            p[c * NF] = run;
            run += t;
        }
    }
}

// ---------------- per-chunk output ------------------------------------------
// out[t] = (qp_t @ S_prefix + sum_{s<=t} (qp_t . kp_s) v_s) / (qp_t . z_prefix + sum_{s<=t} qp_t.kp_s + eps)
#define QPS 132  // padded row stride (floats) for qp/kp in shared
__global__ __launch_bounds__(256) void attn_out_kernel(const float* __restrict__ qp,
                                                       const float* __restrict__ kp,
                                                       const float* __restrict__ v,
                                                       const float* __restrict__ Sp,
                                                       const float* __restrict__ zp,
                                                       float* __restrict__ y) {
    int blk = blockIdx.x;
    int c = blk % NCH, bh = blk / NCH;
    int b = bh / HH, h = bh % HH;

    extern __shared__ float sh[];
    float* qp_sh = sh;                       // 128*132
    float* kp_sh = qp_sh + CC * QPS;         // 128*132
    float* v_sh  = kp_sh + CC * QPS;         // 128*64
    float* S_sh  = v_sh + CC * HD;           // 128*64 (f-major: [f*64+e])
    float* z_sh  = S_sh + NF * HD;           // 128

    int tid = threadIdx.x;
    const float* qp_base = qp + ((size_t)bh * TT + c * CC) * NF;
    const float* kp_base = kp + ((size_t)bh * TT + c * CC) * NF;

    // load qp/kp chunks with padding (float4 granularity)
    for (int i = tid; i < CC * (NF / 4); i += 256) {
        int t = i >> 5, f4 = i & 31;
        ((float4*)qp_sh)[t * (QPS / 4) + f4] = ((const float4*)qp_base)[i];
        ((float4*)kp_sh)[t * (QPS / 4) + f4] = ((const float4*)kp_base)[i];
    }
    for (int i = tid; i < CC * (HD / 4); i += 256) {
        int t = i >> 4, e4 = i & 15;
        ((float4*)v_sh)[i] = *(const float4*)(
            v + (size_t)(b * TT + c * CC + t) * DM + h * HD + e4 * 4);
    }
    const float* S_base = Sp + (size_t)blk * NF * HD;
    for (int i = tid; i < NF * HD / 4; i += 256)
        ((float4*)S_sh)[i] = ((const float4*)S_base)[i];
    for (int i = tid; i < NF / 4; i += 256)
        ((float4*)z_sh)[i] = ((const float4*)(zp + (size_t)blk * NF))[i];
    __syncthreads();

    int r = tid >> 1;          // row within chunk (0..127)
    int e0 = (tid & 1) * 32;   // my half of HD

    float acc[32];
#pragma unroll
    for (int i = 0; i < 32; i++) acc[i] = 0.f;
    float den = 0.f;

    // Stage A: inter-chunk  acc += qp_r . S_prefix ; den += qp_r . z_prefix
#pragma unroll 2
    for (int f = 0; f < NF; f++) {
        float qf = qp_sh[r * QPS + f];
        den += qf * z_sh[f];
        const float4* Srow = (const float4*)(S_sh + f * HD + e0);
#pragma unroll
        for (int i = 0; i < 8; i++) {
            float4 sv = Srow[i];
            acc[4 * i + 0] += qf * sv.x;
            acc[4 * i + 1] += qf * sv.y;
            acc[4 * i + 2] += qf * sv.z;
            acc[4 * i + 3] += qf * sv.w;
        }
    }

    // Stage B: intra-chunk causal part
    const float4* qr4 = (const float4*)(qp_sh + r * QPS);
    for (int s = 0; s <= r; s++) {
        const float4* ks4 = (const float4*)(kp_sh + s * QPS);
        float d0 = 0.f, d1 = 0.f, d2 = 0.f, d3 = 0.f;
#pragma unroll 8
        for (int j = 0; j < 32; j++) {
            float4 a = qr4[j];
            float4 bv = ks4[j];
            d0 += a.x * bv.x;
            d1 += a.y * bv.y;
            d2 += a.z * bv.z;
            d3 += a.w * bv.w;
        }
        float aval = (d0 + d1) + (d2 + d3);
        den += aval;
        const float4* vr = (const float4*)(v_sh + s * HD + e0);
#pragma unroll
        for (int i = 0; i < 8; i++) {
            float4 vv = vr[i];
            acc[4 * i + 0] += aval * vv.x;
            acc[4 * i + 1] += aval * vv.y;
            acc[4 * i + 2] += aval * vv.z;
            acc[4 * i + 3] += aval * vv.w;
        }
    }

    float inv = 1.0f / (den + EPSV);
    float* yo = y + (size_t)(b * TT + c * CC + r) * DM + h * HD + e0;
#pragma unroll
    for (int i = 0; i < 8; i++) {
        float4 o = make_float4(acc[4 * i + 0] * inv, acc[4 * i + 1] * inv,
                               acc[4 * i + 2] * inv, acc[4 * i + 3] * inv);
        ((float4*)yo)[i] = o;
    }
}

// ---------------- launcher ----------------------------------------------------
extern "C" void kernel_launch(void* const* d_in, const int* in_sizes, int n_in,
                              void* d_out, int out_size) {
    const float* x  = (const float*)d_in[0];
    const float* Wq = (const float*)d_in[1];
    const float* Wk = (const float*)d_in[2];
    const float* Wv = (const float*)d_in[3];
    const float* Wo = (const float*)d_in[4];
    const float* Wf = (const float*)d_in[5];
    float* out = (float*)d_out;

    float *pq, *pk, *pv, *py, *pqp, *pkp, *pS, *pz;
    cudaGetSymbolAddress((void**)&pq,  g_q);
    cudaGetSymbolAddress((void**)&pk,  g_k);
    cudaGetSymbolAddress((void**)&pv,  g_v);
    cudaGetSymbolAddress((void**)&py,  g_y);
    cudaGetSymbolAddress((void**)&pqp, g_qp);
    cudaGetSymbolAddress((void**)&pkp, g_kp);
    cudaGetSymbolAddress((void**)&pS,  g_S);
    cudaGetSymbolAddress((void**)&pz,  g_z);

    dim3 gg(DM / GN, ROWS / GM);
    gemm_kernel<<<gg, 256>>>(x, Wq, pq, ROWS, DM, DM);
    gemm_kernel<<<gg, 256>>>(x, Wk, pk, ROWS, DM, DM);
    gemm_kernel<<<gg, 256>>>(x, Wv, pv, ROWS, DM, DM);

    feature_kernel<<<dim3(BHT / FK_ROWS, 2), 128>>>(pq, pk, Wf, pqp, pkp);

    chunk_kv_kernel<<<BB * HH * NCH, 256>>>(pkp, pv, pS, pz);
    prefix_kernel<<<BB * HH, 256>>>(pS, pz);

    int smem5 = (2 * CC * QPS + CC * HD + NF * HD + NF) * (int)sizeof(float);
    cudaFuncSetAttribute(attn_out_kernel,
                         cudaFuncAttributeMaxDynamicSharedMemorySize, smem5);
    attn_out_kernel<<<BB * HH * NCH, 256, smem5>>>(pqp, pkp, pv, pS, pz, py);

    gemm_kernel<<<gg, 256>>>(py, Wo, out, ROWS, DM, DM);
}

// round 4
// speedup vs baseline: 1.5947x; 1.5947x over previous
#include <cuda_runtime.h>
#include <cuda_bf16.h>
#include <math.h>
#include <stdint.h>

// Problem constants
#define BB   4
#define TT   2048
#define DM   1024
#define HH   16
#define HD   64
#define NF   128
#define CC   128              // chunk length
#define NCH  (TT/CC)          // 16 chunks
#define ROWS (BB*TT)          // 8192
#define BHT  (BB*HH*TT)       // 131072
#define EPSV 1e-6f
#define INV_SQRT_NF 0.08838834764831845f

// ---------------- scratch (device globals; no runtime allocation) -------------
__device__ float g_q [ROWS*DM];
__device__ float g_k [ROWS*DM];
__device__ float g_v [ROWS*DM];
__device__ float g_y [ROWS*DM];
__device__ float g_qp[(size_t)BHT*NF];
__device__ float g_kp[(size_t)BHT*NF];
__device__ float g_S [(size_t)BB*HH*NCH*NF*HD];
__device__ float g_z [(size_t)BB*HH*NCH*NF];
__device__ __nv_bfloat16 g_xh[ROWS*DM];
__device__ __nv_bfloat16 g_xl[ROWS*DM];
__device__ __nv_bfloat16 g_yh[ROWS*DM];
__device__ __nv_bfloat16 g_yl[ROWS*DM];
__device__ __nv_bfloat16 g_wh[4*DM*DM];   // transposed weights, hi part  [N,K]
__device__ __nv_bfloat16 g_wl[4*DM*DM];   // transposed weights, lo part  [N,K]

// ======================= PTX helpers ==========================================
__device__ __forceinline__ uint32_t smem_u32(const void* p) {
    uint32_t a;
    asm("{ .reg .u64 t; cvta.to.shared.u64 t, %1; cvt.u32.u64 %0, t; }"
        : "=r"(a) : "l"(p));
    return a;
}
__device__ __forceinline__ void cp16(uint32_t d, const void* g) {
    asm volatile("cp.async.cg.shared.global [%0], [%1], 16;" :: "r"(d), "l"(g));
}
__device__ __forceinline__ void ldm_x4(uint32_t* r, uint32_t a) {
    asm volatile("ldmatrix.sync.aligned.m8n8.x4.shared.b16 {%0,%1,%2,%3}, [%4];"
                 : "=r"(r[0]), "=r"(r[1]), "=r"(r[2]), "=r"(r[3]) : "r"(a));
}
__device__ __forceinline__ void ldm_x2(uint32_t* r, uint32_t a) {
    asm volatile("ldmatrix.sync.aligned.m8n8.x2.shared.b16 {%0,%1}, [%2];"
                 : "=r"(r[0]), "=r"(r[1]) : "r"(a));
}
__device__ __forceinline__ void mma16816(float* c, const uint32_t* a, const uint32_t* b) {
    asm volatile(
        "mma.sync.aligned.m16n8k16.row.col.f32.bf16.bf16.f32 "
        "{%0,%1,%2,%3}, {%4,%5,%6,%7}, {%8,%9}, {%0,%1,%2,%3};"
        : "+f"(c[0]), "+f"(c[1]), "+f"(c[2]), "+f"(c[3])
        : "r"(a[0]), "r"(a[1]), "r"(a[2]), "r"(a[3]), "r"(b[0]), "r"(b[1]));
}

// ======================= bf16 split / transpose ===============================
__global__ __launch_bounds__(256) void split_kernel(const float* __restrict__ x,
                                                    __nv_bfloat16* __restrict__ h,
                                                    __nv_bfloat16* __restrict__ l,
                                                    int n4) {
    int i = blockIdx.x * blockDim.x + threadIdx.x;
    int stride = gridDim.x * blockDim.x;
    for (; i < n4; i += stride) {
        float4 v = ((const float4*)x)[i];
        __nv_bfloat16 h0 = __float2bfloat16(v.x);
        __nv_bfloat16 h1 = __float2bfloat16(v.y);
        __nv_bfloat16 h2 = __float2bfloat16(v.z);
        __nv_bfloat16 h3 = __float2bfloat16(v.w);
        __nv_bfloat16 l0 = __float2bfloat16(v.x - __bfloat162float(h0));
        __nv_bfloat16 l1 = __float2bfloat16(v.y - __bfloat162float(h1));
        __nv_bfloat16 l2 = __float2bfloat16(v.z - __bfloat162float(h2));
        __nv_bfloat16 l3 = __float2bfloat16(v.w - __bfloat162float(h3));
        __nv_bfloat162 ha; ha.x = h0; ha.y = h1;
        __nv_bfloat162 hb; hb.x = h2; hb.y = h3;
        __nv_bfloat162 la; la.x = l0; la.y = l1;
        __nv_bfloat162 lb; lb.x = l2; lb.y = l3;
        ((__nv_bfloat162*)h)[2 * i]     = ha;
        ((__nv_bfloat162*)h)[2 * i + 1] = hb;
        ((__nv_bfloat162*)l)[2 * i]     = la;
        ((__nv_bfloat162*)l)[2 * i + 1] = lb;
    }
}

// W [K=DM, N=DM] row-major  ->  th/tl [N, K] bf16 (hi/lo split)
__global__ __launch_bounds__(256) void wsplit_kernel(const float* __restrict__ W,
                                                     __nv_bfloat16* __restrict__ th,
                                                     __nv_bfloat16* __restrict__ tl) {
    __shared__ float t[32][33];
    int bn = blockIdx.x * 32, bk = blockIdx.y * 32;
    int tx = threadIdx.x & 31, ty = threadIdx.x >> 5;
    for (int r = ty; r < 32; r += 8)
        t[r][tx] = W[(size_t)(bk + r) * DM + bn + tx];
    __syncthreads();
    for (int r = ty; r < 32; r += 8) {
        float v = t[tx][r];                 // = W[bk+tx][bn+r]
        __nv_bfloat16 h = __float2bfloat16(v);
        __nv_bfloat16 l = __float2bfloat16(v - __bfloat162float(h));
        th[(size_t)(bn + r) * DM + bk + tx] = h;
        tl[(size_t)(bn + r) * DM + bk + tx] = l;
    }
}

// ======================= mma.sync bf16x3 GEMM =================================
// C[8192,1024] = (Ah+Al)[M,K] @ (Bh+Bl)^T  (B stored [N,K] row-major)
// computed as Ah*Bh + Al*Bh + Ah*Bl with fp32 accumulators.
// Block tile 128x128x32, 8 warps (4M x 2N), warp tile 32x64.
#define MBK 32
#define MNK (DM / MBK)        // 32 k-iterations
#define MSTAGES 4
#define MROWB 80              // padded row pitch in bytes (40 bf16)
#define MMATB (128 * MROWB)   // 10240 B per matrix tile
#define MSTAGE_B (4 * MMATB)  // 40960 B per stage (Ah, Al, Bh, Bl)
#define MSMEM (MSTAGES * MSTAGE_B)

__device__ __forceinline__ void mload_stage(uint32_t sbase, int tid,
                                            const __nv_bfloat16* ah,
                                            const __nv_bfloat16* al,
                                            const __nv_bfloat16* bh,
                                            const __nv_bfloat16* bl, int k0) {
    // 2048 16B-chunks: mat = j>>1, r = (j&1)*64 + tid/4, ch = tid&3
    int r0 = tid >> 2, ch = tid & 3;
#pragma unroll
    for (int j = 0; j < 8; j++) {
        const __nv_bfloat16* base = (j < 2) ? ah : (j < 4) ? al : (j < 6) ? bh : bl;
        int mat = j >> 1;
        int r = (j & 1) * 64 + r0;
        cp16(sbase + mat * MMATB + r * MROWB + ch * 16,
             base + (size_t)r * DM + k0 + ch * 8);
    }
}

__global__ __launch_bounds__(256, 1) void gemm_mma(
    const __nv_bfloat16* __restrict__ Ah, const __nv_bfloat16* __restrict__ Al,
    const __nv_bfloat16* __restrict__ Bh, const __nv_bfloat16* __restrict__ Bl,
    float* __restrict__ C) {
    extern __shared__ char smem[];
    uint32_t sm = smem_u32(smem);
    int tid = threadIdx.x, lane = tid & 31, wid = tid >> 5;
    int wm = wid & 3, wn = wid >> 2;           // warp tile: rows wm*32, cols wn*64
    int bm = blockIdx.y * 128, bn = blockIdx.x * 128;

    const __nv_bfloat16* pAh = Ah + (size_t)bm * DM;
    const __nv_bfloat16* pAl = Al + (size_t)bm * DM;
    const __nv_bfloat16* pBh = Bh + (size_t)bn * DM;
    const __nv_bfloat16* pBl = Bl + (size_t)bn * DM;

    float acc[2][8][4];
#pragma unroll
    for (int mt = 0; mt < 2; mt++)
#pragma unroll
        for (int nt = 0; nt < 8; nt++)
#pragma unroll
            for (int i = 0; i < 4; i++) acc[mt][nt][i] = 0.f;

    // prologue: fill STAGES-1 stages
#pragma unroll
    for (int s = 0; s < MSTAGES - 1; s++) {
        mload_stage(sm + s * MSTAGE_B, tid, pAh, pAl, pBh, pBl, s * MBK);
        asm volatile("cp.async.commit_group;");
    }

    // per-thread ldmatrix address components
    int a_row = (lane & 15);                   // + wm*32 + mt*16
    int a_koff = (lane >= 16) ? 8 : 0;
    int b_row = (lane & 7);                    // + wn*64 + nt*8
    int b_koff = ((lane & 15) >= 8) ? 8 : 0;

    for (int kt = 0; kt < MNK; kt++) {
        asm volatile("cp.async.wait_group 2;");
        __syncthreads();
        int pf = kt + MSTAGES - 1;
        if (pf < MNK)
            mload_stage(sm + (pf % MSTAGES) * MSTAGE_B, tid, pAh, pAl, pBh, pBl,
                        pf * MBK);
        asm volatile("cp.async.commit_group;");

        uint32_t sbase = sm + (kt % MSTAGES) * MSTAGE_B;
#pragma unroll
        for (int k16 = 0; k16 < 2; k16++) {
            uint32_t ah[2][4], al[2][4];
#pragma unroll
            for (int mt = 0; mt < 2; mt++) {
                uint32_t addr = sbase + (wm * 32 + mt * 16 + a_row) * MROWB +
                                (k16 * 16 + a_koff) * 2;
                ldm_x4(ah[mt], addr);
                ldm_x4(al[mt], addr + MMATB);
            }
            uint32_t bh[8][2], bl[8][2];
#pragma unroll
            for (int nt = 0; nt < 8; nt++) {
                uint32_t addr = sbase + 2 * MMATB +
                                (wn * 64 + nt * 8 + b_row) * MROWB +
                                (k16 * 16 + b_koff) * 2;
                ldm_x2(bh[nt], addr);
                ldm_x2(bl[nt], addr + MMATB);
            }
#pragma unroll
            for (int mt = 0; mt < 2; mt++)
#pragma unroll
                for (int nt = 0; nt < 8; nt++) {
                    mma16816(acc[mt][nt], ah[mt], bh[nt]);
                    mma16816(acc[mt][nt], al[mt], bh[nt]);
                    mma16816(acc[mt][nt], ah[mt], bl[nt]);
                }
        }
    }

    // epilogue: write fp32 C
    int gid = lane >> 2, tig = lane & 3;
#pragma unroll
    for (int mt = 0; mt < 2; mt++) {
        int row = bm + wm * 32 + mt * 16 + gid;
#pragma unroll
        for (int nt = 0; nt < 8; nt++) {
            int col = bn + wn * 64 + nt * 8 + tig * 2;
            float2 c01 = make_float2(acc[mt][nt][0], acc[mt][nt][1]);
            float2 c23 = make_float2(acc[mt][nt][2], acc[mt][nt][3]);
            *(float2*)(C + (size_t)row * DM + col) = c01;
            *(float2*)(C + (size_t)(row + 8) * DM + col) = c23;
        }
    }
}

// ---------------- FAVOR+ feature map -----------------------------------------
__global__ __launch_bounds__(256) void feature_kernel(const float* __restrict__ q,
                                                      const float* __restrict__ k,
                                                      const float* __restrict__ Wf,
                                                      float* __restrict__ qp,
                                                      float* __restrict__ kp) {
    const float* src = blockIdx.y ? k : q;
    float* dst = blockIdx.y ? kp : qp;
    __shared__ float Wfs[NF * 68];      // [f][d], padded
    __shared__ float qs[32][68];        // 32 rows, padded
    __shared__ float sq[32];
    int tid = threadIdx.x;

    for (int i = tid; i < HD * NF; i += 256) {
        int d = i >> 7, f = i & 127;
        Wfs[f * 68 + d] = Wf[i];
    }
    int row0 = blockIdx.x * 32;
    for (int i = tid; i < 32 * HD; i += 256) {
        int rr = i >> 6, d = i & 63;
        int row = row0 + rr;
        int bh = row / TT, t = row % TT;
        int b = bh >> 4, h = bh & 15;
        qs[rr][d] = src[(size_t)(b * TT + t) * DM + h * HD + d];
    }
    __syncthreads();
    if (tid < 32) {
        float s = 0.f;
#pragma unroll
        for (int d = 0; d < HD; d++) { float v = qs[tid][d]; s += v * v; }
        sq[tid] = 0.5f * s;
    }
    __syncthreads();

    int f = tid & 127, half = tid >> 7;
    const float4* wrow = (const float4*)(Wfs + f * 68);
#pragma unroll 4
    for (int rr16 = 0; rr16 < 16; rr16++) {
        int rr = half * 16 + rr16;
        const float4* qrow = (const float4*)(&qs[rr][0]);
        float d0 = 0.f, d1 = 0.f;
#pragma unroll
        for (int j = 0; j < 16; j++) {
            float4 w = wrow[j];
            float4 qv = qrow[j];
            d0 += w.x * qv.x + w.y * qv.y;
            d1 += w.z * qv.z + w.w * qv.w;
        }
        dst[(size_t)(row0 + rr) * NF + f] = expf((d0 + d1) - sq[rr]) * INV_SQRT_NF;
    }
}

// ---------------- per-chunk local K^T V and sum(k) ----------------------------
__global__ __launch_bounds__(256) void chunk_kv_kernel(const float* __restrict__ kp,
                                                       const float* __restrict__ v,
                                                       float* __restrict__ Sc,
                                                       float* __restrict__ zc) {
    int blk = blockIdx.x;
    int c = blk % NCH, bh = blk / NCH;
    int b = bh / HH, h = bh % HH;
    __shared__ float kps[16 * NF];
    __shared__ float vs[16 * HD];
    int tid = threadIdx.x;
    int e0 = (tid & 15) * 4;
    int f0 = tid >> 4;   // 0..15

    float acc[8][4];
#pragma unroll
    for (int j = 0; j < 8; j++)
#pragma unroll
        for (int i = 0; i < 4; i++) acc[j][i] = 0.f;

    const float* kp_base = kp + ((size_t)bh * TT + c * CC) * NF;

    for (int tt = 0; tt < CC / 16; tt++) {
        __syncthreads();
        for (int i = tid; i < 16 * NF / 4; i += 256)
            ((float4*)kps)[i] = ((const float4*)(kp_base + tt * 16 * NF))[i];
        for (int i = tid; i < 16 * HD / 4; i += 256) {
            int t = i >> 4, e4 = i & 15;
            ((float4*)vs)[i] = *(const float4*)(
                v + (size_t)(b * TT + c * CC + tt * 16 + t) * DM + h * HD + e4 * 4);
        }
        __syncthreads();
#pragma unroll 4
        for (int t = 0; t < 16; t++) {
            float4 vv = *(const float4*)(vs + t * HD + e0);
#pragma unroll
            for (int j = 0; j < 8; j++) {
                float kf = kps[t * NF + f0 + 16 * j];
                acc[j][0] += kf * vv.x;
                acc[j][1] += kf * vv.y;
                acc[j][2] += kf * vv.z;
                acc[j][3] += kf * vv.w;
            }
        }
    }
    float* Sbase = Sc + (size_t)blk * NF * HD;
#pragma unroll
    for (int j = 0; j < 8; j++) {
        int f = f0 + 16 * j;
        *(float4*)(Sbase + f * HD + e0) =
            make_float4(acc[j][0], acc[j][1], acc[j][2], acc[j][3]);
    }
    __syncthreads();
    if (tid < NF) {
        float zz = 0.f;
        for (int t = 0; t < CC; t++) zz += kp_base[t * NF + tid];
        zc[(size_t)blk * NF + tid] = zz;
    }
}

// ---------------- exclusive prefix over chunks (per bh stream) ----------------
__global__ __launch_bounds__(256) void prefix_kernel(float* __restrict__ Sc,
                                                     float* __restrict__ zc) {
    int bh = blockIdx.x;
    int tid = threadIdx.x;
    for (int idx = tid; idx < NF * HD; idx += 256) {
        float run = 0.f;
        float* p = Sc + (size_t)bh * NCH * NF * HD + idx;
        for (int c = 0; c < NCH; c++) {
            float t = p[(size_t)c * NF * HD];
            p[(size_t)c * NF * HD] = run;
            run += t;
        }
    }
    for (int idx = tid; idx < NF; idx += 256) {
        float run = 0.f;
        float* p = zc + (size_t)bh * NCH * NF + idx;
        for (int c = 0; c < NCH; c++) {
            float t = p[c * NF];
            p[c * NF] = run;
            run += t;
        }
    }
}

// ---------------- per-chunk output ------------------------------------------
#define QPS 132  // padded row stride (floats) for qp/kp in shared
__global__ __launch_bounds__(256) void attn_out_kernel(const float* __restrict__ qp,
                                                       const float* __restrict__ kp,
                                                       const float* __restrict__ v,
                                                       const float* __restrict__ Sp,
                                                       const float* __restrict__ zp,
                                                       float* __restrict__ y) {
    int blk = blockIdx.x;
    int c = blk % NCH, bh = blk / NCH;
    int b = bh / HH, h = bh % HH;

    extern __shared__ float sh[];
    float* qp_sh = sh;                       // 128*132
    float* kp_sh = qp_sh + CC * QPS;         // 128*132
    float* v_sh  = kp_sh + CC * QPS;         // 128*64
    float* S_sh  = v_sh + CC * HD;           // 128*64 (f-major: [f*64+e])
    float* z_sh  = S_sh + NF * HD;           // 128

    int tid = threadIdx.x;
    const float* qp_base = qp + ((size_t)bh * TT + c * CC) * NF;
    const float* kp_base = kp + ((size_t)bh * TT + c * CC) * NF;

    for (int i = tid; i < CC * (NF / 4); i += 256) {
        int t = i >> 5, f4 = i & 31;
        ((float4*)qp_sh)[t * (QPS / 4) + f4] = ((const float4*)qp_base)[i];
        ((float4*)kp_sh)[t * (QPS / 4) + f4] = ((const float4*)kp_base)[i];
    }
    for (int i = tid; i < CC * (HD / 4); i += 256) {
        int t = i >> 4, e4 = i & 15;
        ((float4*)v_sh)[i] = *(const float4*)(
            v + (size_t)(b * TT + c * CC + t) * DM + h * HD + e4 * 4);
    }
    const float* S_base = Sp + (size_t)blk * NF * HD;
    for (int i = tid; i < NF * HD / 4; i += 256)
        ((float4*)S_sh)[i] = ((const float4*)S_base)[i];
    for (int i = tid; i < NF / 4; i += 256)
        ((float4*)z_sh)[i] = ((const float4*)(zp + (size_t)blk * NF))[i];
    __syncthreads();

    int r = tid >> 1;          // row within chunk (0..127)
    int e0 = (tid & 1) * 32;   // my half of HD

    float acc[32];
#pragma unroll
    for (int i = 0; i < 32; i++) acc[i] = 0.f;
    float den = 0.f;

#pragma unroll 2
    for (int f = 0; f < NF; f++) {
        float qf = qp_sh[r * QPS + f];
        den += qf * z_sh[f];
        const float4* Srow = (const float4*)(S_sh + f * HD + e0);
#pragma unroll
        for (int i = 0; i < 8; i++) {
            float4 sv = Srow[i];
            acc[4 * i + 0] += qf * sv.x;
            acc[4 * i + 1] += qf * sv.y;
            acc[4 * i + 2] += qf * sv.z;
            acc[4 * i + 3] += qf * sv.w;
        }
    }

    const float4* qr4 = (const float4*)(qp_sh + r * QPS);
    for (int s = 0; s <= r; s++) {
        const float4* ks4 = (const float4*)(kp_sh + s * QPS);
        float d0 = 0.f, d1 = 0.f, d2 = 0.f, d3 = 0.f;
#pragma unroll 8
        for (int j = 0; j < 32; j++) {
            float4 a = qr4[j];
            float4 bv = ks4[j];
            d0 += a.x * bv.x;
            d1 += a.y * bv.y;
            d2 += a.z * bv.z;
            d3 += a.w * bv.w;
        }
        float aval = (d0 + d1) + (d2 + d3);
        den += aval;
        const float4* vr = (const float4*)(v_sh + s * HD + e0);
#pragma unroll
        for (int i = 0; i < 8; i++) {
            float4 vv = vr[i];
            acc[4 * i + 0] += aval * vv.x;
            acc[4 * i + 1] += aval * vv.y;
            acc[4 * i + 2] += aval * vv.z;
            acc[4 * i + 3] += aval * vv.w;
        }
    }

    float inv = 1.0f / (den + EPSV);
    float* yo = y + (size_t)(b * TT + c * CC + r) * DM + h * HD + e0;
#pragma unroll
    for (int i = 0; i < 8; i++) {
        float4 o = make_float4(acc[4 * i + 0] * inv, acc[4 * i + 1] * inv,
                               acc[4 * i + 2] * inv, acc[4 * i + 3] * inv);
        ((float4*)yo)[i] = o;
    }
}

// ---------------- launcher ----------------------------------------------------
extern "C" void kernel_launch(void* const* d_in, const int* in_sizes, int n_in,
                              void* d_out, int out_size) {
    const float* x  = (const float*)d_in[0];
    const float* Wq = (const float*)d_in[1];
    const float* Wk = (const float*)d_in[2];
    const float* Wv = (const float*)d_in[3];
    const float* Wo = (const float*)d_in[4];
    const float* Wf = (const float*)d_in[5];
    float* out = (float*)d_out;

    float *pq, *pk, *pv, *py, *pqp, *pkp, *pS, *pz;
    __nv_bfloat16 *pxh, *pxl, *pyh, *pyl, *pwh, *pwl;
    cudaGetSymbolAddress((void**)&pq,  g_q);
    cudaGetSymbolAddress((void**)&pk,  g_k);
    cudaGetSymbolAddress((void**)&pv,  g_v);
    cudaGetSymbolAddress((void**)&py,  g_y);
    cudaGetSymbolAddress((void**)&pqp, g_qp);
    cudaGetSymbolAddress((void**)&pkp, g_kp);
    cudaGetSymbolAddress((void**)&pS,  g_S);
    cudaGetSymbolAddress((void**)&pz,  g_z);
    cudaGetSymbolAddress((void**)&pxh, g_xh);
    cudaGetSymbolAddress((void**)&pxl, g_xl);
    cudaGetSymbolAddress((void**)&pyh, g_yh);
    cudaGetSymbolAddress((void**)&pyl, g_yl);
    cudaGetSymbolAddress((void**)&pwh, g_wh);
    cudaGetSymbolAddress((void**)&pwl, g_wl);

    cudaFuncSetAttribute(gemm_mma, cudaFuncAttributeMaxDynamicSharedMemorySize,
                         MSMEM);
    int smem5 = (2 * CC * QPS + CC * HD + NF * HD + NF) * (int)sizeof(float);
    cudaFuncSetAttribute(attn_out_kernel,
                         cudaFuncAttributeMaxDynamicSharedMemorySize, smem5);

    // 1. split x into bf16 hi/lo
    split_kernel<<<2048, 256>>>(x, pxh, pxl, ROWS * DM / 4);
    // 2. transpose + split weights -> [N,K] bf16 hi/lo
    dim3 wg(DM / 32, DM / 32);
    wsplit_kernel<<<wg, 256>>>(Wq, pwh + 0 * (size_t)DM * DM, pwl + 0 * (size_t)DM * DM);
    wsplit_kernel<<<wg, 256>>>(Wk, pwh + 1 * (size_t)DM * DM, pwl + 1 * (size_t)DM * DM);
    wsplit_kernel<<<wg, 256>>>(Wv, pwh + 2 * (size_t)DM * DM, pwl + 2 * (size_t)DM * DM);
    wsplit_kernel<<<wg, 256>>>(Wo, pwh + 3 * (size_t)DM * DM, pwl + 3 * (size_t)DM * DM);

    // 3. tensor-core projections (mma.sync)
    dim3 gg(DM / 128, ROWS / 128);   // (8, 64)
    gemm_mma<<<gg, 256, MSMEM>>>(pxh, pxl, pwh + 0 * (size_t)DM * DM, pwl + 0 * (size_t)DM * DM, pq);
    gemm_mma<<<gg, 256, MSMEM>>>(pxh, pxl, pwh + 1 * (size_t)DM * DM, pwl + 1 * (size_t)DM * DM, pk);
    gemm_mma<<<gg, 256, MSMEM>>>(pxh, pxl, pwh + 2 * (size_t)DM * DM, pwl + 2 * (size_t)DM * DM, pv);

    // 4. feature map + attention
    feature_kernel<<<dim3(BHT / 32, 2), 256>>>(pq, pk, Wf, pqp, pkp);
    chunk_kv_kernel<<<BB * HH * NCH, 256>>>(pkp, pv, pS, pz);
    prefix_kernel<<<BB * HH, 256>>>(pS, pz);
    attn_out_kernel<<<BB * HH * NCH, 256, smem5>>>(pqp, pkp, pv, pS, pz, py);

    // 5. output projection
    split_kernel<<<2048, 256>>>(py, pyh, pyl, ROWS * DM / 4);
    gemm_mma<<<gg, 256, MSMEM>>>(pyh, pyl, pwh + 3 * (size_t)DM * DM, pwl + 3 * (size_t)DM * DM, out);
}

// round 5
// speedup vs baseline: 2.2117x; 1.3869x over previous
#include <cuda_runtime.h>
#include <cuda_bf16.h>
#include <math.h>
#include <stdint.h>

// Problem constants
#define BB   4
#define TT   2048
#define DM   1024
#define HH   16
#define HD   64
#define NF   128
#define CC   128
#define NCH  (TT/CC)          // 16
#define ROWS (BB*TT)          // 8192
#define BHT  (BB*HH*TT)       // 131072
#define EPSV 1e-6f
#define INV_SQRT_NF 0.08838834764831845f

// ---------------- scratch (device globals) ------------------------------------
__device__ float g_q [ROWS*DM];
__device__ float g_k [ROWS*DM];
__device__ float g_S [(size_t)BB*HH*NCH*NF*HD];
__device__ float g_z [(size_t)BB*HH*NCH*NF];
__device__ __nv_bfloat16 g_xh[ROWS*DM];
__device__ __nv_bfloat16 g_xl[ROWS*DM];
__device__ __nv_bfloat16 g_vh[ROWS*DM];
__device__ __nv_bfloat16 g_vl[ROWS*DM];
__device__ __nv_bfloat16 g_yh[ROWS*DM];
__device__ __nv_bfloat16 g_yl[ROWS*DM];
__device__ __nv_bfloat16 g_qph[(size_t)BHT*NF];
__device__ __nv_bfloat16 g_qpl[(size_t)BHT*NF];
__device__ __nv_bfloat16 g_kph[(size_t)BHT*NF];
__device__ __nv_bfloat16 g_kpl[(size_t)BHT*NF];
__device__ __nv_bfloat16 g_wh[4*DM*DM];   // transposed weights hi  [N,K]
__device__ __nv_bfloat16 g_wl[4*DM*DM];   // transposed weights lo  [N,K]

// ======================= PTX helpers ==========================================
__device__ __forceinline__ uint32_t smem_u32(const void* p) {
    uint32_t a;
    asm("{ .reg .u64 t; cvta.to.shared.u64 t, %1; cvt.u32.u64 %0, t; }"
        : "=r"(a) : "l"(p));
    return a;
}
__device__ __forceinline__ void cp16(uint32_t d, const void* g) {
    asm volatile("cp.async.cg.shared.global [%0], [%1], 16;" :: "r"(d), "l"(g));
}
__device__ __forceinline__ void ldm_x4(uint32_t* r, uint32_t a) {
    asm volatile("ldmatrix.sync.aligned.m8n8.x4.shared.b16 {%0,%1,%2,%3}, [%4];"
                 : "=r"(r[0]), "=r"(r[1]), "=r"(r[2]), "=r"(r[3]) : "r"(a));
}
__device__ __forceinline__ void ldm_x4t(uint32_t* r, uint32_t a) {
    asm volatile("ldmatrix.sync.aligned.m8n8.x4.trans.shared.b16 {%0,%1,%2,%3}, [%4];"
                 : "=r"(r[0]), "=r"(r[1]), "=r"(r[2]), "=r"(r[3]) : "r"(a));
}
__device__ __forceinline__ void mma16816(float* c, const uint32_t* a, const uint32_t* b) {
    asm volatile(
        "mma.sync.aligned.m16n8k16.row.col.f32.bf16.bf16.f32 "
        "{%0,%1,%2,%3}, {%4,%5,%6,%7}, {%8,%9}, {%0,%1,%2,%3};"
        : "+f"(c[0]), "+f"(c[1]), "+f"(c[2]), "+f"(c[3])
        : "r"(a[0]), "r"(a[1]), "r"(a[2]), "r"(a[3]), "r"(b[0]), "r"(b[1]));
}
__device__ __forceinline__ __nv_bfloat162 split_pair(float a, float b,
                                                     __nv_bfloat162& lo) {
    __nv_bfloat16 h0 = __float2bfloat16(a);
    __nv_bfloat16 h1 = __float2bfloat16(b);
    __nv_bfloat16 l0 = __float2bfloat16(a - __bfloat162float(h0));
    __nv_bfloat16 l1 = __float2bfloat16(b - __bfloat162float(h1));
    lo.x = l0; lo.y = l1;
    __nv_bfloat162 hi; hi.x = h0; hi.y = h1;
    return hi;
}

// ======================= bf16 split / transpose ===============================
__global__ __launch_bounds__(256) void split_kernel(const float* __restrict__ x,
                                                    __nv_bfloat16* __restrict__ h,
                                                    __nv_bfloat16* __restrict__ l,
                                                    int n4) {
    int i = blockIdx.x * blockDim.x + threadIdx.x;
    int stride = gridDim.x * blockDim.x;
    for (; i < n4; i += stride) {
        float4 v = ((const float4*)x)[i];
        __nv_bfloat162 la, lb;
        __nv_bfloat162 ha = split_pair(v.x, v.y, la);
        __nv_bfloat162 hb = split_pair(v.z, v.w, lb);
        ((__nv_bfloat162*)h)[2 * i]     = ha;
        ((__nv_bfloat162*)h)[2 * i + 1] = hb;
        ((__nv_bfloat162*)l)[2 * i]     = la;
        ((__nv_bfloat162*)l)[2 * i + 1] = lb;
    }
}

__global__ __launch_bounds__(256) void wsplit_kernel(const float* __restrict__ W,
                                                     __nv_bfloat16* __restrict__ th,
                                                     __nv_bfloat16* __restrict__ tl) {
    __shared__ float t[32][33];
    int bn = blockIdx.x * 32, bk = blockIdx.y * 32;
    int tx = threadIdx.x & 31, ty = threadIdx.x >> 5;
    for (int r = ty; r < 32; r += 8)
        t[r][tx] = W[(size_t)(bk + r) * DM + bn + tx];
    __syncthreads();
    for (int r = ty; r < 32; r += 8) {
        float v = t[tx][r];
        __nv_bfloat16 h = __float2bfloat16(v);
        __nv_bfloat16 l = __float2bfloat16(v - __bfloat162float(h));
        th[(size_t)(bn + r) * DM + bk + tx] = h;
        tl[(size_t)(bn + r) * DM + bk + tx] = l;
    }
}

// ======================= mma.sync bf16x3 GEMM =================================
#define MBK 32
#define MNK (DM / MBK)
#define MSTAGES 4
#define MROWB 80
#define MMATB (128 * MROWB)
#define MSTAGE_B (4 * MMATB)
#define MSMEM (MSTAGES * MSTAGE_B)

__device__ __forceinline__ void mload_stage(uint32_t sbase, int tid,
                                            const __nv_bfloat16* ah,
                                            const __nv_bfloat16* al,
                                            const __nv_bfloat16* bh,
                                            const __nv_bfloat16* bl, int k0) {
    int r0 = tid >> 2, ch = tid & 3;
#pragma unroll
    for (int j = 0; j < 8; j++) {
        const __nv_bfloat16* base = (j < 2) ? ah : (j < 4) ? al : (j < 6) ? bh : bl;
        int mat = j >> 1;
        int r = (j & 1) * 64 + r0;
        cp16(sbase + mat * MMATB + r * MROWB + ch * 16,
             base + (size_t)r * DM + k0 + ch * 8);
    }
}

// MODE 0: write fp32 C.  MODE 1: write bf16 hi/lo to Ch/Cl.
template <int MODE>
__global__ __launch_bounds__(256, 1) void gemm_mma(
    const __nv_bfloat16* __restrict__ Ah, const __nv_bfloat16* __restrict__ Al,
    const __nv_bfloat16* __restrict__ Bh, const __nv_bfloat16* __restrict__ Bl,
    float* __restrict__ C, __nv_bfloat16* __restrict__ Ch,
    __nv_bfloat16* __restrict__ Cl) {
    extern __shared__ char smem[];
    uint32_t sm = smem_u32(smem);
    int tid = threadIdx.x, lane = tid & 31, wid = tid >> 5;
    int wm = wid & 3, wn = wid >> 2;
    int bm = blockIdx.y * 128, bn = blockIdx.x * 128;

    const __nv_bfloat16* pAh = Ah + (size_t)bm * DM;
    const __nv_bfloat16* pAl = Al + (size_t)bm * DM;
    const __nv_bfloat16* pBh = Bh + (size_t)bn * DM;
    const __nv_bfloat16* pBl = Bl + (size_t)bn * DM;

    float acc[2][8][4];
#pragma unroll
    for (int mt = 0; mt < 2; mt++)
#pragma unroll
        for (int nt = 0; nt < 8; nt++)
#pragma unroll
            for (int i = 0; i < 4; i++) acc[mt][nt][i] = 0.f;

#pragma unroll
    for (int s = 0; s < MSTAGES - 1; s++) {
        mload_stage(sm + s * MSTAGE_B, tid, pAh, pAl, pBh, pBl, s * MBK);
        asm volatile("cp.async.commit_group;");
    }

    int a_row = (lane & 15);
    int a_koff = (lane >= 16) ? 8 : 0;
    int b_row = (lane & 7) + ((lane >> 4) << 3);
    int b_koff = ((lane >> 3) & 1) * 8;

    for (int kt = 0; kt < MNK; kt++) {
        asm volatile("cp.async.wait_group 2;");
        __syncthreads();
        int pf = kt + MSTAGES - 1;
        if (pf < MNK)
            mload_stage(sm + (pf % MSTAGES) * MSTAGE_B, tid, pAh, pAl, pBh, pBl,
                        pf * MBK);
        asm volatile("cp.async.commit_group;");

        uint32_t sbase = sm + (kt % MSTAGES) * MSTAGE_B;
#pragma unroll
        for (int k16 = 0; k16 < 2; k16++) {
            uint32_t fah[2][4], fal[2][4];
#pragma unroll
            for (int mt = 0; mt < 2; mt++) {
                uint32_t addr = sbase + (wm * 32 + mt * 16 + a_row) * MROWB +
                                (k16 * 16 + a_koff) * 2;
                ldm_x4(fah[mt], addr);
                ldm_x4(fal[mt], addr + MMATB);
            }
            uint32_t fbh[8][2], fbl[8][2];
#pragma unroll
            for (int ntp = 0; ntp < 4; ntp++) {
                uint32_t addr = sbase + 2 * MMATB +
                                (wn * 64 + ntp * 16 + b_row) * MROWB +
                                (k16 * 16 + b_koff) * 2;
                uint32_t t4[4];
                ldm_x4(t4, addr);
                fbh[2 * ntp][0] = t4[0]; fbh[2 * ntp][1] = t4[1];
                fbh[2 * ntp + 1][0] = t4[2]; fbh[2 * ntp + 1][1] = t4[3];
                ldm_x4(t4, addr + MMATB);
                fbl[2 * ntp][0] = t4[0]; fbl[2 * ntp][1] = t4[1];
                fbl[2 * ntp + 1][0] = t4[2]; fbl[2 * ntp + 1][1] = t4[3];
            }
#pragma unroll
            for (int mt = 0; mt < 2; mt++)
#pragma unroll
                for (int nt = 0; nt < 8; nt++) {
                    mma16816(acc[mt][nt], fah[mt], fbh[nt]);
                    mma16816(acc[mt][nt], fal[mt], fbh[nt]);
                    mma16816(acc[mt][nt], fah[mt], fbl[nt]);
                }
        }
    }

    int gid = lane >> 2, tig = lane & 3;
#pragma unroll
    for (int mt = 0; mt < 2; mt++) {
#pragma unroll
        for (int nt = 0; nt < 8; nt++) {
#pragma unroll
            for (int rh = 0; rh < 2; rh++) {
                int row = bm + wm * 32 + mt * 16 + gid + rh * 8;
                int col = bn + wn * 64 + nt * 8 + tig * 2;
                float c0 = acc[mt][nt][2 * rh], c1 = acc[mt][nt][2 * rh + 1];
                if (MODE == 0) {
                    *(float2*)(C + (size_t)row * DM + col) = make_float2(c0, c1);
                } else {
                    __nv_bfloat162 lo;
                    __nv_bfloat162 hi = split_pair(c0, c1, lo);
                    *(__nv_bfloat162*)(Ch + (size_t)row * DM + col) = hi;
                    *(__nv_bfloat162*)(Cl + (size_t)row * DM + col) = lo;
                }
            }
        }
    }
}

// ---------------- FAVOR+ feature map (reg-cached W, bf16 h/l output) ---------
__global__ __launch_bounds__(256) void feature_kernel(
    const float* __restrict__ q, const float* __restrict__ k,
    const float* __restrict__ Wf,
    __nv_bfloat16* __restrict__ qph, __nv_bfloat16* __restrict__ qpl,
    __nv_bfloat16* __restrict__ kph, __nv_bfloat16* __restrict__ kpl) {
    const float* src = blockIdx.y ? k : q;
    __nv_bfloat16* dh = blockIdx.y ? kph : qph;
    __nv_bfloat16* dl = blockIdx.y ? kpl : qpl;
    __shared__ float Wfs[NF * 68];
    __shared__ float qs[32][68];
    __shared__ float sq[32];
    int tid = threadIdx.x;

    for (int i = tid; i < HD * NF; i += 256) {
        int d = i >> 7, f = i & 127;
        Wfs[f * 68 + d] = Wf[i];
    }
    int row0 = blockIdx.x * 32;
    for (int i = tid; i < 32 * HD; i += 256) {
        int rr = i >> 6, d = i & 63;
        int row = row0 + rr;
        int bh = row / TT, t = row % TT;
        int b = bh >> 4, h = bh & 15;
        qs[rr][d] = src[(size_t)(b * TT + t) * DM + h * HD + d];
    }
    __syncthreads();
    if (tid < 32) {
        float s = 0.f;
#pragma unroll
        for (int d = 0; d < HD; d++) { float v = qs[tid][d]; s += v * v; }
        sq[tid] = 0.5f * s;
    }
    __syncthreads();

    int f = tid & 127, rbase = (tid >> 7) * 16;
    float4 w[16];
#pragma unroll
    for (int j = 0; j < 16; j++) w[j] = ((const float4*)(Wfs + f * 68))[j];

#pragma unroll
    for (int rc = 0; rc < 2; rc++) {
        float acc[8];
#pragma unroll
        for (int r8 = 0; r8 < 8; r8++) acc[r8] = 0.f;
#pragma unroll
        for (int j = 0; j < 16; j++) {
#pragma unroll
            for (int r8 = 0; r8 < 8; r8++) {
                float4 qv = ((const float4*)(&qs[rbase + rc * 8 + r8][0]))[j];
                acc[r8] += w[j].x * qv.x + w[j].y * qv.y + w[j].z * qv.z +
                           w[j].w * qv.w;
            }
        }
#pragma unroll
        for (int r8 = 0; r8 < 8; r8++) {
            int rr = rbase + rc * 8 + r8;
            float val = expf(acc[r8] - sq[rr]) * INV_SQRT_NF;
            __nv_bfloat16 h16 = __float2bfloat16(val);
            __nv_bfloat16 l16 = __float2bfloat16(val - __bfloat162float(h16));
            size_t o = (size_t)(row0 + rr) * NF + f;
            dh[o] = h16;
            dl[o] = l16;
        }
    }
}

// ---------------- per-chunk local K^T V and sum(k) ----------------------------
__global__ __launch_bounds__(256) void chunk_kv_kernel(
    const __nv_bfloat16* __restrict__ kph, const __nv_bfloat16* __restrict__ kpl,
    const __nv_bfloat16* __restrict__ vh, const __nv_bfloat16* __restrict__ vl,
    float* __restrict__ Sc, float* __restrict__ zc) {
    int blk = blockIdx.x;
    int c = blk % NCH, bh = blk / NCH;
    int b = bh / HH, h = bh % HH;
    __shared__ float kps[16 * NF];
    __shared__ float vs[16 * HD];
    int tid = threadIdx.x;
    int e0 = (tid & 15) * 4;
    int f0 = tid >> 4;

    float acc[8][4];
#pragma unroll
    for (int j = 0; j < 8; j++)
#pragma unroll
        for (int i = 0; i < 4; i++) acc[j][i] = 0.f;

    const __nv_bfloat16* kh_base = kph + ((size_t)bh * TT + c * CC) * NF;
    const __nv_bfloat16* kl_base = kpl + ((size_t)bh * TT + c * CC) * NF;

    for (int tt = 0; tt < CC / 16; tt++) {
        __syncthreads();
        for (int i = tid; i < 16 * NF / 4; i += 256) {
            const __nv_bfloat162* ph = (const __nv_bfloat162*)(kh_base + tt * 16 * NF + i * 4);
            const __nv_bfloat162* pl = (const __nv_bfloat162*)(kl_base + tt * 16 * NF + i * 4);
            __nv_bfloat162 h0 = ph[0], h1 = ph[1], l0 = pl[0], l1 = pl[1];
            float4 r;
            r.x = __low2float(h0) + __low2float(l0);
            r.y = __high2float(h0) + __high2float(l0);
            r.z = __low2float(h1) + __low2float(l1);
            r.w = __high2float(h1) + __high2float(l1);
            ((float4*)kps)[i] = r;
        }
        for (int i = tid; i < 16 * HD / 4; i += 256) {
            int t = i >> 4, e4 = i & 15;
            size_t off = (size_t)(b * TT + c * CC + tt * 16 + t) * DM + h * HD + e4 * 4;
            const __nv_bfloat162* ph = (const __nv_bfloat162*)(vh + off);
            const __nv_bfloat162* pl = (const __nv_bfloat162*)(vl + off);
            __nv_bfloat162 h0 = ph[0], h1 = ph[1], l0 = pl[0], l1 = pl[1];
            float4 r;
            r.x = __low2float(h0) + __low2float(l0);
            r.y = __high2float(h0) + __high2float(l0);
            r.z = __low2float(h1) + __low2float(l1);
            r.w = __high2float(h1) + __high2float(l1);
            ((float4*)vs)[i] = r;
        }
        __syncthreads();
#pragma unroll 4
        for (int t = 0; t < 16; t++) {
            float4 vv = *(const float4*)(vs + t * HD + e0);
#pragma unroll
            for (int j = 0; j < 8; j++) {
                float kf = kps[t * NF + f0 + 16 * j];
                acc[j][0] += kf * vv.x;
                acc[j][1] += kf * vv.y;
                acc[j][2] += kf * vv.z;
                acc[j][3] += kf * vv.w;
            }
        }
    }
    float* Sbase = Sc + (size_t)blk * NF * HD;
#pragma unroll
    for (int j = 0; j < 8; j++) {
        int f = f0 + 16 * j;
        *(float4*)(Sbase + f * HD + e0) =
            make_float4(acc[j][0], acc[j][1], acc[j][2], acc[j][3]);
    }
    __syncthreads();
    if (tid < NF) {
        float zz = 0.f;
        for (int t = 0; t < CC; t++)
            zz += __bfloat162float(kh_base[t * NF + tid]) +
                  __bfloat162float(kl_base[t * NF + tid]);
        zc[(size_t)blk * NF + tid] = zz;
    }
}

// ---------------- exclusive prefix over chunks --------------------------------
__global__ __launch_bounds__(256) void prefix_kernel(float* __restrict__ Sc,
                                                     float* __restrict__ zc) {
    int bh = blockIdx.x;
    int tid = threadIdx.x;
    for (int idx = tid; idx < NF * HD; idx += 256) {
        float run = 0.f;
        float* p = Sc + (size_t)bh * NCH * NF * HD + idx;
        for (int c = 0; c < NCH; c++) {
            float t = p[(size_t)c * NF * HD];
            p[(size_t)c * NF * HD] = run;
            run += t;
        }
    }
    for (int idx = tid; idx < NF; idx += 256) {
        float run = 0.f;
        float* p = zc + (size_t)bh * NCH * NF + idx;
        for (int c = 0; c < NCH; c++) {
            float t = p[c * NF];
            p[c * NF] = run;
            run += t;
        }
    }
}

// ---------------- MMA attention chunk kernel ----------------------------------
// Phase 1: A = qp @ kp^T (128x128x128, 3xbf16, fp32 acc), causal mask,
//          split -> bf16 h/l (stored into kp's smem region).
// den[t] = rowsum(A_masked) + qp[t].z
// Phase 2: O = [A | qp] (128x256) @ [[V],[S_prefix]] (256x64), y = O/den.
#define PQE 136
#define PQB (PQE * 2)
#define PVE 72
#define PVB (PVE * 2)
#define OQH 0
#define OQL (OQH + 128 * PQB)          // 34816
#define OKH (OQL + 128 * PQB)          // 69632  (kp, later A)
#define OKL (OKH + 128 * PQB)          // 104448
#define OVH (OKL + 128 * PQB)          // 139264
#define OVL (OVH + 128 * PVB)          // 157696
#define OSH (OVL + 128 * PVB)          // 176128
#define OSL (OSH + 128 * PVB)          // 194560
#define ODEN (OSL + 128 * PVB)         // 212992
#define OZ  (ODEN + 512)               // 213504
#define ATTN_SMEM (OZ + 512)           // 214016

__global__ __launch_bounds__(256, 1) void attn_mma_kernel(
    const __nv_bfloat16* __restrict__ qph, const __nv_bfloat16* __restrict__ qpl,
    const __nv_bfloat16* __restrict__ kph, const __nv_bfloat16* __restrict__ kpl,
    const __nv_bfloat16* __restrict__ vh, const __nv_bfloat16* __restrict__ vl,
    const float* __restrict__ Sp, const float* __restrict__ zp,
    __nv_bfloat16* __restrict__ yh, __nv_bfloat16* __restrict__ yl) {
    int blk = blockIdx.x;
    int c = blk % NCH, bh = blk / NCH;
    int b = bh / HH, h = bh % HH;

    extern __shared__ char smem[];
    uint32_t sm = smem_u32(smem);
    int tid = threadIdx.x, lane = tid & 31, wid = tid >> 5;

    // ---- load qp/kp (bf16, 128x128) ----
    {
        size_t base = ((size_t)bh * TT + c * CC) * NF;
        const uint4* sqh = (const uint4*)(qph + base);
        const uint4* sql = (const uint4*)(qpl + base);
        const uint4* skh = (const uint4*)(kph + base);
        const uint4* skl = (const uint4*)(kpl + base);
        for (int i = tid; i < 2048; i += 256) {
            int row = i >> 4, c8 = i & 15;
            int off = row * PQB + c8 * 16;
            *(uint4*)(smem + OQH + off) = sqh[i];
            *(uint4*)(smem + OQL + off) = sql[i];
            *(uint4*)(smem + OKH + off) = skh[i];
            *(uint4*)(smem + OKL + off) = skl[i];
        }
        // V 128x64 bf16
        for (int i = tid; i < 1024; i += 256) {
            int row = i >> 3, c8 = i & 7;
            size_t go = (size_t)(b * TT + c * CC + row) * DM + h * HD + c8 * 8;
            *(uint4*)(smem + OVH + row * PVB + c8 * 16) = *(const uint4*)(vh + go);
            *(uint4*)(smem + OVL + row * PVB + c8 * 16) = *(const uint4*)(vl + go);
        }
        // S_prefix 128x64 fp32 -> split h/l
        const float4* sS = (const float4*)(Sp + (size_t)blk * NF * HD);
        for (int i = tid; i < 2048; i += 256) {
            int row = i >> 4, c4 = i & 15;
            float4 v = sS[i];
            __nv_bfloat162 l0, l1;
            __nv_bfloat162 h0 = split_pair(v.x, v.y, l0);
            __nv_bfloat162 h1 = split_pair(v.z, v.w, l1);
            uint2 hv, lv;
            hv.x = *(uint32_t*)&h0; hv.y = *(uint32_t*)&h1;
            lv.x = *(uint32_t*)&l0; lv.y = *(uint32_t*)&l1;
            *(uint2*)(smem + OSH + row * PVB + c4 * 8) = hv;
            *(uint2*)(smem + OSL + row * PVB + c4 * 8) = lv;
        }
        const float4* sz = (const float4*)(zp + (size_t)blk * NF);
        for (int i = tid; i < 32; i += 256)
            ((float4*)(smem + OZ))[i] = sz[i];
    }
    __syncthreads();

    int wm = wid & 3, wn = wid >> 2;
    int gid = lane >> 2, tig = lane & 3;
    int a_row = lane & 15, a_koff = (lane >= 16) ? 8 : 0;
    int b_row = (lane & 7) + ((lane >> 4) << 3);
    int b_koff = ((lane >> 3) & 1) * 8;

    // ---- phase 1: A = qp @ kp^T ----
    float accA[2][8][4];
#pragma unroll
    for (int mt = 0; mt < 2; mt++)
#pragma unroll
        for (int nt = 0; nt < 8; nt++)
#pragma unroll
            for (int i = 0; i < 4; i++) accA[mt][nt][i] = 0.f;

#pragma unroll
    for (int kt = 0; kt < 8; kt++) {
        uint32_t fah[2][4], fal[2][4];
#pragma unroll
        for (int mt = 0; mt < 2; mt++) {
            uint32_t addr = sm + OQH + (wm * 32 + mt * 16 + a_row) * PQB +
                            (kt * 16 + a_koff) * 2;
            ldm_x4(fah[mt], addr);
            ldm_x4(fal[mt], addr + (OQL - OQH));
        }
        uint32_t fbh[8][2], fbl[8][2];
#pragma unroll
        for (int ntp = 0; ntp < 4; ntp++) {
            uint32_t addr = sm + OKH + (wn * 64 + ntp * 16 + b_row) * PQB +
                            (kt * 16 + b_koff) * 2;
            uint32_t t4[4];
            ldm_x4(t4, addr);
            fbh[2 * ntp][0] = t4[0]; fbh[2 * ntp][1] = t4[1];
            fbh[2 * ntp + 1][0] = t4[2]; fbh[2 * ntp + 1][1] = t4[3];
            ldm_x4(t4, addr + (OKL - OKH));
            fbl[2 * ntp][0] = t4[0]; fbl[2 * ntp][1] = t4[1];
            fbl[2 * ntp + 1][0] = t4[2]; fbl[2 * ntp + 1][1] = t4[3];
        }
#pragma unroll
        for (int mt = 0; mt < 2; mt++)
#pragma unroll
            for (int nt = 0; nt < 8; nt++) {
                mma16816(accA[mt][nt], fah[mt], fbh[nt]);
                mma16816(accA[mt][nt], fal[mt], fbh[nt]);
                mma16816(accA[mt][nt], fah[mt], fbl[nt]);
            }
    }
    __syncthreads();   // everyone done reading kp

    // mask + split-store A into kp region
#pragma unroll
    for (int mt = 0; mt < 2; mt++)
#pragma unroll
        for (int nt = 0; nt < 8; nt++)
#pragma unroll
            for (int rh = 0; rh < 2; rh++) {
                int row = wm * 32 + mt * 16 + gid + rh * 8;
                int col = wn * 64 + nt * 8 + tig * 2;
                float c0 = accA[mt][nt][2 * rh], c1 = accA[mt][nt][2 * rh + 1];
                if (col > row) c0 = 0.f;
                if (col + 1 > row) c1 = 0.f;
                __nv_bfloat162 lo;
                __nv_bfloat162 hi = split_pair(c0, c1, lo);
                *(__nv_bfloat162*)(smem + OKH + row * PQB + col * 2) = hi;
                *(__nv_bfloat162*)(smem + OKL + row * PQB + col * 2) = lo;
            }
    __syncthreads();

    // den[t] = rowsum(A) + qp[t].z
    if (tid < 128) {
        const __nv_bfloat16* ah_ = (const __nv_bfloat16*)(smem + OKH + tid * PQB);
        const __nv_bfloat16* al_ = (const __nv_bfloat16*)(smem + OKL + tid * PQB);
        const __nv_bfloat16* qh_ = (const __nv_bfloat16*)(smem + OQH + tid * PQB);
        const __nv_bfloat16* ql_ = (const __nv_bfloat16*)(smem + OQL + tid * PQB);
        const float* zf = (const float*)(smem + OZ);
        float s = 0.f;
        for (int j = 0; j < NF; j++)
            s += __bfloat162float(ah_[j]) + __bfloat162float(al_[j]);
        for (int j = 0; j < NF; j++)
            s += (__bfloat162float(qh_[j]) + __bfloat162float(ql_[j])) * zf[j];
        ((float*)(smem + ODEN))[tid] = s;
    }
    __syncthreads();

    // ---- phase 2: O = [A | qp] @ [[V],[S]] ----
    float accO[2][4][4];
#pragma unroll
    for (int mt = 0; mt < 2; mt++)
#pragma unroll
        for (int nt = 0; nt < 4; nt++)
#pragma unroll
            for (int i = 0; i < 4; i++) accO[mt][nt][i] = 0.f;

    int bt_row = (lane & 7) + ((lane >> 3) & 1) * 8;
    int bt_nt = lane >> 4;

#pragma unroll
    for (int kt = 0; kt < 16; kt++) {
        int isA = (kt < 8);
        uint32_t abase = isA ? OKH : OQH;
        uint32_t abl = isA ? OKL : OQL;
        uint32_t bbase = isA ? OVH : OSH;
        uint32_t bbl = isA ? OVL : OSL;
        int kk = (kt & 7) * 16;
        uint32_t fah[2][4], fal[2][4];
#pragma unroll
        for (int mt = 0; mt < 2; mt++) {
            uint32_t addr = sm + abase + (wm * 32 + mt * 16 + a_row) * PQB +
                            (kk + a_koff) * 2;
            ldm_x4(fah[mt], addr);
            ldm_x4(fal[mt], addr + (abl - abase));
        }
        uint32_t fbh[4][2], fbl[4][2];
#pragma unroll
        for (int ntp = 0; ntp < 2; ntp++) {
            uint32_t addr = sm + bbase + (kk + bt_row) * PVB +
                            (wn * 32 + ntp * 16 + bt_nt * 8) * 2;
            uint32_t t4[4];
            ldm_x4t(t4, addr);
            fbh[2 * ntp][0] = t4[0]; fbh[2 * ntp][1] = t4[1];
            fbh[2 * ntp + 1][0] = t4[2]; fbh[2 * ntp + 1][1] = t4[3];
            ldm_x4t(t4, addr + (bbl - bbase));
            fbl[2 * ntp][0] = t4[0]; fbl[2 * ntp][1] = t4[1];
            fbl[2 * ntp + 1][0] = t4[2]; fbl[2 * ntp + 1][1] = t4[3];
        }
#pragma unroll
        for (int mt = 0; mt < 2; mt++)
#pragma unroll
            for (int nt = 0; nt < 4; nt++) {
                mma16816(accO[mt][nt], fah[mt], fbh[nt]);
                mma16816(accO[mt][nt], fal[mt], fbh[nt]);
                mma16816(accO[mt][nt], fah[mt], fbl[nt]);
            }
    }

    // epilogue: divide by den, split, write yh/yl
    const float* den = (const float*)(smem + ODEN);
#pragma unroll
    for (int mt = 0; mt < 2; mt++)
#pragma unroll
        for (int nt = 0; nt < 4; nt++)
#pragma unroll
            for (int rh = 0; rh < 2; rh++) {
                int row = wm * 32 + mt * 16 + gid + rh * 8;
                int col = wn * 32 + nt * 8 + tig * 2;
                float inv = 1.0f / (den[row] + EPSV);
                float v0 = accO[mt][nt][2 * rh] * inv;
                float v1 = accO[mt][nt][2 * rh + 1] * inv;
                __nv_bfloat162 lo;
                __nv_bfloat162 hi = split_pair(v0, v1, lo);
                size_t go = (size_t)(b * TT + c * CC + row) * DM + h * HD + col;
                *(__nv_bfloat162*)(yh + go) = hi;
                *(__nv_bfloat162*)(yl + go) = lo;
            }
}

// ---------------- launcher ----------------------------------------------------
extern "C" void kernel_launch(void* const* d_in, const int* in_sizes, int n_in,
                              void* d_out, int out_size) {
    const float* x  = (const float*)d_in[0];
    const float* Wq = (const float*)d_in[1];
    const float* Wk = (const float*)d_in[2];
    const float* Wv = (const float*)d_in[3];
    const float* Wo = (const float*)d_in[4];
    const float* Wf = (const float*)d_in[5];
    float* out = (float*)d_out;

    float *pq, *pk, *pS, *pz;
    __nv_bfloat16 *pxh, *pxl, *pvh, *pvl, *pyh, *pyl, *pwh, *pwl;
    __nv_bfloat16 *pqph, *pqpl, *pkph, *pkpl;
    cudaGetSymbolAddress((void**)&pq,  g_q);
    cudaGetSymbolAddress((void**)&pk,  g_k);
    cudaGetSymbolAddress((void**)&pS,  g_S);
    cudaGetSymbolAddress((void**)&pz,  g_z);
    cudaGetSymbolAddress((void**)&pxh, g_xh);
    cudaGetSymbolAddress((void**)&pxl, g_xl);
    cudaGetSymbolAddress((void**)&pvh, g_vh);
    cudaGetSymbolAddress((void**)&pvl, g_vl);
    cudaGetSymbolAddress((void**)&pyh, g_yh);
    cudaGetSymbolAddress((void**)&pyl, g_yl);
    cudaGetSymbolAddress((void**)&pwh, g_wh);
    cudaGetSymbolAddress((void**)&pwl, g_wl);
    cudaGetSymbolAddress((void**)&pqph, g_qph);
    cudaGetSymbolAddress((void**)&pqpl, g_qpl);
    cudaGetSymbolAddress((void**)&pkph, g_kph);
    cudaGetSymbolAddress((void**)&pkpl, g_kpl);

    cudaFuncSetAttribute(gemm_mma<0>, cudaFuncAttributeMaxDynamicSharedMemorySize, MSMEM);
    cudaFuncSetAttribute(gemm_mma<1>, cudaFuncAttributeMaxDynamicSharedMemorySize, MSMEM);
    cudaFuncSetAttribute(attn_mma_kernel, cudaFuncAttributeMaxDynamicSharedMemorySize, ATTN_SMEM);

    // 1. split x into bf16 hi/lo
    split_kernel<<<2048, 256>>>(x, pxh, pxl, ROWS * DM / 4);
    // 2. transpose + split weights
    dim3 wg(DM / 32, DM / 32);
    wsplit_kernel<<<wg, 256>>>(Wq, pwh + 0 * (size_t)DM * DM, pwl + 0 * (size_t)DM * DM);
    wsplit_kernel<<<wg, 256>>>(Wk, pwh + 1 * (size_t)DM * DM, pwl + 1 * (size_t)DM * DM);
    wsplit_kernel<<<wg, 256>>>(Wv, pwh + 2 * (size_t)DM * DM, pwl + 2 * (size_t)DM * DM);
    wsplit_kernel<<<wg, 256>>>(Wo, pwh + 3 * (size_t)DM * DM, pwl + 3 * (size_t)DM * DM);

    // 3. projections
    dim3 gg(DM / 128, ROWS / 128);
    gemm_mma<0><<<gg, 256, MSMEM>>>(pxh, pxl, pwh + 0 * (size_t)DM * DM, pwl + 0 * (size_t)DM * DM, pq, nullptr, nullptr);
    gemm_mma<0><<<gg, 256, MSMEM>>>(pxh, pxl, pwh + 1 * (size_t)DM * DM, pwl + 1 * (size_t)DM * DM, pk, nullptr, nullptr);
    gemm_mma<1><<<gg, 256, MSMEM>>>(pxh, pxl, pwh + 2 * (size_t)DM * DM, pwl + 2 * (size_t)DM * DM, nullptr, pvh, pvl);

    // 4. feature map + attention
    feature_kernel<<<dim3(BHT / 32, 2), 256>>>(pq, pk, Wf, pqph, pqpl, pkph, pkpl);
    chunk_kv_kernel<<<BB * HH * NCH, 256>>>(pkph, pkpl, pvh, pvl, pS, pz);
    prefix_kernel<<<BB * HH, 256>>>(pS, pz);
    attn_mma_kernel<<<BB * HH * NCH, 256, ATTN_SMEM>>>(pqph, pqpl, pkph, pkpl,
                                                       pvh, pvl, pS, pz, pyh, pyl);

    // 5. output projection
    gemm_mma<0><<<gg, 256, MSMEM>>>(pyh, pyl, pwh + 3 * (size_t)DM * DM, pwl + 3 * (size_t)DM * DM, out, nullptr, nullptr);
}

// round 9
// speedup vs baseline: 2.6938x; 1.2180x over previous
#include <cuda_runtime.h>
#include <cuda_bf16.h>
#include <math.h>
#include <stdint.h>

// Problem constants
#define BB   4
#define TT   2048
#define DM   1024
#define HH   16
#define HD   64
#define NF   128
#define CC   128
#define NCH  (TT/CC)          // 16
#define ROWS (BB*TT)          // 8192
#define BHT  (BB*HH*TT)       // 131072
#define EPSV 1e-6f
#define INV_SQRT_NF 0.08838834764831845f

// ---------------- scratch (device globals) ------------------------------------
__device__ float g_q [ROWS*DM];
__device__ float g_k [ROWS*DM];
__device__ float g_S [(size_t)BB*HH*NCH*NF*HD];
__device__ float g_z [(size_t)BB*HH*NCH*NF];
__device__ __nv_bfloat16 g_xh[ROWS*DM];
__device__ __nv_bfloat16 g_xl[ROWS*DM];
__device__ __nv_bfloat16 g_vh[ROWS*DM];
__device__ __nv_bfloat16 g_vl[ROWS*DM];
__device__ __nv_bfloat16 g_yh[ROWS*DM];
__device__ __nv_bfloat16 g_yl[ROWS*DM];
__device__ __nv_bfloat16 g_qph[(size_t)BHT*NF];
__device__ __nv_bfloat16 g_qpl[(size_t)BHT*NF];
__device__ __nv_bfloat16 g_kph[(size_t)BHT*NF];
__device__ __nv_bfloat16 g_kpl[(size_t)BHT*NF];
__device__ __nv_bfloat16 g_wh[4*DM*DM];   // transposed weights hi [4096,1024]
__device__ __nv_bfloat16 g_wl[4*DM*DM];   // transposed weights lo

// ======================= PTX helpers ==========================================
__device__ __forceinline__ uint32_t smem_u32(const void* p) {
    uint32_t a;
    asm("{ .reg .u64 t; cvta.to.shared.u64 t, %1; cvt.u32.u64 %0, t; }"
        : "=r"(a) : "l"(p));
    return a;
}
__device__ __forceinline__ void cp16(uint32_t d, const void* g) {
    asm volatile("cp.async.cg.shared.global [%0], [%1], 16;" :: "r"(d), "l"(g));
}
__device__ __forceinline__ void ldm_x4(uint32_t* r, uint32_t a) {
    asm volatile("ldmatrix.sync.aligned.m8n8.x4.shared.b16 {%0,%1,%2,%3}, [%4];"
                 : "=r"(r[0]), "=r"(r[1]), "=r"(r[2]), "=r"(r[3]) : "r"(a));
}
__device__ __forceinline__ void ldm_x4t(uint32_t* r, uint32_t a) {
    asm volatile("ldmatrix.sync.aligned.m8n8.x4.trans.shared.b16 {%0,%1,%2,%3}, [%4];"
                 : "=r"(r[0]), "=r"(r[1]), "=r"(r[2]), "=r"(r[3]) : "r"(a));
}
__device__ __forceinline__ void mma16816(float* c, const uint32_t* a, const uint32_t* b) {
    asm volatile(
        "mma.sync.aligned.m16n8k16.row.col.f32.bf16.bf16.f32 "
        "{%0,%1,%2,%3}, {%4,%5,%6,%7}, {%8,%9}, {%0,%1,%2,%3};"
        : "+f"(c[0]), "+f"(c[1]), "+f"(c[2]), "+f"(c[3])
        : "r"(a[0]), "r"(a[1]), "r"(a[2]), "r"(a[3]), "r"(b[0]), "r"(b[1]));
}
__device__ __forceinline__ __nv_bfloat162 split_pair(float a, float b,
                                                     __nv_bfloat162& lo) {
    __nv_bfloat16 h0 = __float2bfloat16(a);
    __nv_bfloat16 h1 = __float2bfloat16(b);
    __nv_bfloat16 l0 = __float2bfloat16(a - __bfloat162float(h0));
    __nv_bfloat16 l1 = __float2bfloat16(b - __bfloat162float(h1));
    lo.x = l0; lo.y = l1;
    __nv_bfloat162 hi; hi.x = h0; hi.y = h1;
    return hi;
}

// ======================= bf16 split / transpose ===============================
__global__ __launch_bounds__(256) void split_kernel(const float* __restrict__ x,
                                                    __nv_bfloat16* __restrict__ h,
                                                    __nv_bfloat16* __restrict__ l,
                                                    int n4) {
    int i = blockIdx.x * blockDim.x + threadIdx.x;
    int stride = gridDim.x * blockDim.x;
    for (; i < n4; i += stride) {
        float4 v = ((const float4*)x)[i];
        __nv_bfloat162 la, lb;
        __nv_bfloat162 ha = split_pair(v.x, v.y, la);
        __nv_bfloat162 hb = split_pair(v.z, v.w, lb);
        ((__nv_bfloat162*)h)[2 * i]     = ha;
        ((__nv_bfloat162*)h)[2 * i + 1] = hb;
        ((__nv_bfloat162*)l)[2 * i]     = la;
        ((__nv_bfloat162*)l)[2 * i + 1] = lb;
    }
}

__global__ __launch_bounds__(256) void wsplit_kernel(const float* __restrict__ W,
                                                     __nv_bfloat16* __restrict__ th,
                                                     __nv_bfloat16* __restrict__ tl) {
    __shared__ float t[32][33];
    int bn = blockIdx.x * 32, bk = blockIdx.y * 32;
    int tx = threadIdx.x & 31, ty = threadIdx.x >> 5;
    for (int r = ty; r < 32; r += 8)
        t[r][tx] = W[(size_t)(bk + r) * DM + bn + tx];
    __syncthreads();
    for (int r = ty; r < 32; r += 8) {
        float v = t[tx][r];
        __nv_bfloat16 h = __float2bfloat16(v);
        __nv_bfloat16 l = __float2bfloat16(v - __bfloat162float(h));
        th[(size_t)(bn + r) * DM + bk + tx] = h;
        tl[(size_t)(bn + r) * DM + bk + tx] = l;
    }
}

// ======================= big-tile mma.sync bf16x3 GEMM ========================
// Block tile 128x256x32, 8 warps (2M x 4N), warp tile 64x64, 3 stages.
#define BGM 128
#define BGN 256
#define BGK 32
#define BNK (DM / BGK)            // 32
#define BROWB 80
#define BSA_H 0
#define BSA_L (128 * BROWB)       // 10240
#define BSB_H (2 * 128 * BROWB)   // 20480
#define BSB_L (BSB_H + 256 * BROWB)
#define BSTAGE_B (BSB_L + 256 * BROWB)   // 61440
#define BSMEM (3 * BSTAGE_B)             // 184320

__device__ __forceinline__ void bload_stage(uint32_t sbase, int tid,
                                            const __nv_bfloat16* ah,
                                            const __nv_bfloat16* al,
                                            const __nv_bfloat16* bh,
                                            const __nv_bfloat16* bl, int k0) {
    int r0 = tid >> 2, ch = tid & 3;
#pragma unroll
    for (int j = 0; j < 4; j++) {
        const __nv_bfloat16* base = (j < 2) ? ah : al;
        int r = (j & 1) * 64 + r0;
        cp16(sbase + ((j < 2) ? BSA_H : BSA_L) + r * BROWB + ch * 16,
             base + (size_t)r * DM + k0 + ch * 8);
    }
#pragma unroll
    for (int j = 0; j < 8; j++) {
        const __nv_bfloat16* base = (j < 4) ? bh : bl;
        int r = (j & 3) * 64 + r0;
        cp16(sbase + ((j < 4) ? BSB_H : BSB_L) + r * BROWB + ch * 16,
             base + (size_t)r * DM + k0 + ch * 8);
    }
}

// MODE 0: all columns fp32 -> Cq.   MODE 1: QKV mixed (q,k fp32; v bf16 h/l).
template <int MODE>
__global__ __launch_bounds__(256, 1) void gemm_big(
    const __nv_bfloat16* __restrict__ Ah, const __nv_bfloat16* __restrict__ Al,
    const __nv_bfloat16* __restrict__ Bh, const __nv_bfloat16* __restrict__ Bl,
    float* __restrict__ Cq, float* __restrict__ Ck,
    __nv_bfloat16* __restrict__ Cvh, __nv_bfloat16* __restrict__ Cvl) {
    extern __shared__ char smem[];
    uint32_t sm = smem_u32(smem);
    int tid = threadIdx.x, lane = tid & 31, wid = tid >> 5;
    int wm = wid & 1, wn = wid >> 1;
    int bm = blockIdx.y * BGM, bn = blockIdx.x * BGN;

    const __nv_bfloat16* pAh = Ah + (size_t)bm * DM;
    const __nv_bfloat16* pAl = Al + (size_t)bm * DM;
    const __nv_bfloat16* pBh = Bh + (size_t)bn * DM;
    const __nv_bfloat16* pBl = Bl + (size_t)bn * DM;

    float acc[4][8][4];
#pragma unroll
    for (int mt = 0; mt < 4; mt++)
#pragma unroll
        for (int nt = 0; nt < 8; nt++)
#pragma unroll
            for (int i = 0; i < 4; i++) acc[mt][nt][i] = 0.f;

#pragma unroll
    for (int s = 0; s < 2; s++) {
        bload_stage(sm + s * BSTAGE_B, tid, pAh, pAl, pBh, pBl, s * BGK);
        asm volatile("cp.async.commit_group;");
    }

    int a_row = lane & 15;
    int a_koff = (lane >= 16) ? 8 : 0;
    int b_row = (lane & 7) + ((lane >> 4) << 3);
    int b_koff = ((lane >> 3) & 1) * 8;

    for (int kt = 0; kt < BNK; kt++) {
        asm volatile("cp.async.wait_group 1;");
        __syncthreads();
        int pf = kt + 2;
        if (pf < BNK)
            bload_stage(sm + (pf % 3) * BSTAGE_B, tid, pAh, pAl, pBh, pBl,
                        pf * BGK);
        asm volatile("cp.async.commit_group;");

        uint32_t sb = sm + (kt % 3) * BSTAGE_B;
#pragma unroll
        for (int k16 = 0; k16 < 2; k16++) {
            uint32_t fah[4][4], fal[4][4];
#pragma unroll
            for (int mt = 0; mt < 4; mt++) {
                uint32_t addr = sb + BSA_H + (wm * 64 + mt * 16 + a_row) * BROWB +
                                (k16 * 16 + a_koff) * 2;
                ldm_x4(fah[mt], addr);
                ldm_x4(fal[mt], addr + (BSA_L - BSA_H));
            }
            uint32_t fbh[8][2], fbl[8][2];
#pragma unroll
            for (int ntp = 0; ntp < 4; ntp++) {
                uint32_t addr = sb + BSB_H + (wn * 64 + ntp * 16 + b_row) * BROWB +
                                (k16 * 16 + b_koff) * 2;
                uint32_t t4[4];
                ldm_x4(t4, addr);
                fbh[2 * ntp][0] = t4[0]; fbh[2 * ntp][1] = t4[1];
                fbh[2 * ntp + 1][0] = t4[2]; fbh[2 * ntp + 1][1] = t4[3];
                ldm_x4(t4, addr + (BSB_L - BSB_H));
                fbl[2 * ntp][0] = t4[0]; fbl[2 * ntp][1] = t4[1];
                fbl[2 * ntp + 1][0] = t4[2]; fbl[2 * ntp + 1][1] = t4[3];
            }
#pragma unroll
            for (int mt = 0; mt < 4; mt++)
#pragma unroll
                for (int nt = 0; nt < 8; nt++) {
                    mma16816(acc[mt][nt], fah[mt], fbh[nt]);
                    mma16816(acc[mt][nt], fal[mt], fbh[nt]);
                    mma16816(acc[mt][nt], fah[mt], fbl[nt]);
                }
        }
    }

    int gid = lane >> 2, tig = lane & 3;
#pragma unroll
    for (int mt = 0; mt < 4; mt++) {
#pragma unroll
        for (int nt = 0; nt < 8; nt++) {
#pragma unroll
            for (int rh = 0; rh < 2; rh++) {
                int row = bm + wm * 64 + mt * 16 + gid + rh * 8;
                int colg = bn + wn * 64 + nt * 8 + tig * 2;
                float c0 = acc[mt][nt][2 * rh], c1 = acc[mt][nt][2 * rh + 1];
                if (MODE == 0) {
                    *(float2*)(Cq + (size_t)row * DM + colg) = make_float2(c0, c1);
                } else {
                    int region = colg >> 10, cl = colg & 1023;
                    if (region == 0) {
                        *(float2*)(Cq + (size_t)row * DM + cl) = make_float2(c0, c1);
                    } else if (region == 1) {
                        *(float2*)(Ck + (size_t)row * DM + cl) = make_float2(c0, c1);
                    } else {
                        __nv_bfloat162 lo;
                        __nv_bfloat162 hi = split_pair(c0, c1, lo);
                        *(__nv_bfloat162*)(Cvh + (size_t)row * DM + cl) = hi;
                        *(__nv_bfloat162*)(Cvl + (size_t)row * DM + cl) = lo;
                    }
                }
            }
        }
    }
}

// ---------------- FAVOR+ feature map via MMA ----------------------------------
// Block: 128 rows of one bh stream. qp = exp(q@Wf - ||q||^2/2)*inv_sqrt_nf.
#define FQF 0
#define FQH 34816
#define FQL (FQH + 18432)
#define FWH (FQL + 18432)
#define FWL (FWH + 18432)
#define FSQ (FWL + 18432)
#define FSMEM (FSQ + 512)

__global__ __launch_bounds__(256, 1) void feature_mma_kernel(
    const float* __restrict__ q, const float* __restrict__ k,
    const float* __restrict__ Wf,
    __nv_bfloat16* __restrict__ qph, __nv_bfloat16* __restrict__ qpl,
    __nv_bfloat16* __restrict__ kph, __nv_bfloat16* __restrict__ kpl) {
    const float* src = blockIdx.y ? k : q;
    __nv_bfloat16* dh = blockIdx.y ? kph : qph;
    __nv_bfloat16* dl = blockIdx.y ? kpl : qpl;

    extern __shared__ char smem[];
    uint32_t sm = smem_u32(smem);
    int tid = threadIdx.x, lane = tid & 31, wid = tid >> 5;
    int row0 = blockIdx.x * 128;
    int bh = row0 / TT, t0 = row0 % TT;
    int b = bh >> 4, h = bh & 15;

    float* qf = (float*)(smem + FQF);       // [128][68]
    const float* base = src + ((size_t)(b * TT + t0)) * DM + h * HD;
    for (int i = tid; i < 2048; i += 256) {
        int r = i >> 4, c4 = i & 15;
        *(float4*)(qf + r * 68 + c4 * 4) = *(const float4*)(base + (size_t)r * DM + c4 * 4);
    }
    // W_feat split + transpose -> [f][d]
    for (int i = tid; i < 8192; i += 256) {
        int d = i >> 7, f = i & 127;
        float v = Wf[i];
        __nv_bfloat16 h16 = __float2bfloat16(v);
        __nv_bfloat16 l16 = __float2bfloat16(v - __bfloat162float(h16));
        ((__nv_bfloat16*)(smem + FWH))[f * 72 + d] = h16;
        ((__nv_bfloat16*)(smem + FWL))[f * 72 + d] = l16;
    }
    __syncthreads();
    if (tid < 128) {
        float s = 0.f;
        const float4* qr = (const float4*)(qf + tid * 68);
#pragma unroll
        for (int j = 0; j < 16; j++) {
            float4 v = qr[j];
            s += v.x * v.x + v.y * v.y + v.z * v.z + v.w * v.w;
        }
        ((float*)(smem + FSQ))[tid] = 0.5f * s;
    }
    // split q -> bf16 h/l
    for (int i = tid; i < 4096; i += 256) {
        int r = i >> 5, c2 = i & 31;
        float2 v = *(float2*)(qf + r * 68 + c2 * 2);
        __nv_bfloat162 lo;
        __nv_bfloat162 hi = split_pair(v.x, v.y, lo);
        *(__nv_bfloat162*)(smem + FQH + r * 144 + c2 * 4) = hi;
        *(__nv_bfloat162*)(smem + FQL + r * 144 + c2 * 4) = lo;
    }
    __syncthreads();

    int wm = wid & 3, wn = wid >> 2;   // warp tile 32 rows x 64 f
    int a_row = lane & 15, a_koff = (lane >= 16) ? 8 : 0;
    int b_row = (lane & 7) + ((lane >> 4) << 3);
    int b_koff = ((lane >> 3) & 1) * 8;

    float acc[2][8][4];
#pragma unroll
    for (int mt = 0; mt < 2; mt++)
#pragma unroll
        for (int nt = 0; nt < 8; nt++)
#pragma unroll
            for (int i = 0; i < 4; i++) acc[mt][nt][i] = 0.f;

#pragma unroll
    for (int kt = 0; kt < 4; kt++) {
        uint32_t fah[2][4], fal[2][4];
#pragma unroll
        for (int mt = 0; mt < 2; mt++) {
            uint32_t addr = sm + FQH + (wm * 32 + mt * 16 + a_row) * 144 +
                            (kt * 16 + a_koff) * 2;
            ldm_x4(fah[mt], addr);
            ldm_x4(fal[mt], addr + (FQL - FQH));
        }
        uint32_t fbh[8][2], fbl[8][2];
#pragma unroll
        for (int ntp = 0; ntp < 4; ntp++) {
            uint32_t addr = sm + FWH + (wn * 64 + ntp * 16 + b_row) * 144 +
                            (kt * 16 + b_koff) * 2;
            uint32_t t4[4];
            ldm_x4(t4, addr);
            fbh[2 * ntp][0] = t4[0]; fbh[2 * ntp][1] = t4[1];
            fbh[2 * ntp + 1][0] = t4[2]; fbh[2 * ntp + 1][1] = t4[3];
            ldm_x4(t4, addr + (FWL - FWH));
            fbl[2 * ntp][0] = t4[0]; fbl[2 * ntp][1] = t4[1];
            fbl[2 * ntp + 1][0] = t4[2]; fbl[2 * ntp + 1][1] = t4[3];
        }
#pragma unroll
        for (int mt = 0; mt < 2; mt++)
#pragma unroll
            for (int nt = 0; nt < 8; nt++) {
                mma16816(acc[mt][nt], fah[mt], fbh[nt]);
                mma16816(acc[mt][nt], fal[mt], fbh[nt]);
                mma16816(acc[mt][nt], fah[mt], fbl[nt]);
            }
    }

    const float* sq = (const float*)(smem + FSQ);
    int gid = lane >> 2, tig = lane & 3;
#pragma unroll
    for (int mt = 0; mt < 2; mt++)
#pragma unroll
        for (int nt = 0; nt < 8; nt++)
#pragma unroll
            for (int rh = 0; rh < 2; rh++) {
                int row = wm * 32 + mt * 16 + gid + rh * 8;
                int f = wn * 64 + nt * 8 + tig * 2;
                float s = sq[row];
                float v0 = expf(acc[mt][nt][2 * rh] - s) * INV_SQRT_NF;
                float v1 = expf(acc[mt][nt][2 * rh + 1] - s) * INV_SQRT_NF;
                __nv_bfloat162 lo;
                __nv_bfloat162 hi = split_pair(v0, v1, lo);
                size_t o = (size_t)(row0 + row) * NF + f;
                *(__nv_bfloat162*)(dh + o) = hi;
                *(__nv_bfloat162*)(dl + o) = lo;
            }
}

// ---------------- per-chunk K^T V via MMA -------------------------------------
#define CKH 0
#define CKL 34816
#define CVH 69632
#define CVL (CVH + 18432)
#define CZP (CVL + 18432)
#define CSMEM (CZP + 1024)

__global__ __launch_bounds__(256, 1) void chunk_kv_mma(
    const __nv_bfloat16* __restrict__ kph, const __nv_bfloat16* __restrict__ kpl,
    const __nv_bfloat16* __restrict__ vh, const __nv_bfloat16* __restrict__ vl,
    float* __restrict__ Sc, float* __restrict__ zc) {
    int blk = blockIdx.x;
    int c = blk % NCH, bh = blk / NCH;
    int b = bh / HH, h = bh % HH;

    extern __shared__ char smem[];
    uint32_t sm = smem_u32(smem);
    int tid = threadIdx.x, lane = tid & 31, wid = tid >> 5;

    size_t gbase = ((size_t)bh * TT + c * CC) * NF;
    for (int i = tid; i < 2048; i += 256) {
        int r = i >> 4, c8 = i & 15;
        *(uint4*)(smem + CKH + r * 272 + c8 * 16) = ((const uint4*)(kph + gbase))[i];
        *(uint4*)(smem + CKL + r * 272 + c8 * 16) = ((const uint4*)(kpl + gbase))[i];
    }
    for (int i = tid; i < 1024; i += 256) {
        int r = i >> 3, c8 = i & 7;
        size_t go = (size_t)(b * TT + c * CC + r) * DM + h * HD + c8 * 8;
        *(uint4*)(smem + CVH + r * 144 + c8 * 16) = *(const uint4*)(vh + go);
        *(uint4*)(smem + CVL + r * 144 + c8 * 16) = *(const uint4*)(vl + go);
    }
    __syncthreads();

    // z partial sums
    {
        int f = tid & 127, half = tid >> 7;
        float s = 0.f;
        const __nv_bfloat16* kh_ = (const __nv_bfloat16*)(smem + CKH);
        const __nv_bfloat16* kl_ = (const __nv_bfloat16*)(smem + CKL);
        for (int t = half * 64; t < half * 64 + 64; t++)
            s += __bfloat162float(kh_[t * 136 + f]) + __bfloat162float(kl_[t * 136 + f]);
        ((float*)(smem + CZP))[half * 128 + f] = s;
    }

    int wm = wid & 3, wn = (wid >> 2) & 1;   // warp tile 32f x 32e
    int f0 = wm * 32, e0 = wn * 32;
    int r7 = lane & 7, oct = lane >> 3;
    int krow = r7 + ((oct >> 1) & 1) * 8;
    int mcol = (oct & 1) * 8;
    int bt_row = (lane & 7) + ((lane >> 3) & 1) * 8;
    int bt_nt = lane >> 4;

    float acc[2][4][4];
#pragma unroll
    for (int mt = 0; mt < 2; mt++)
#pragma unroll
        for (int nt = 0; nt < 4; nt++)
#pragma unroll
            for (int i = 0; i < 4; i++) acc[mt][nt][i] = 0.f;

#pragma unroll
    for (int kt = 0; kt < 8; kt++) {
        int t0 = kt * 16;
        uint32_t fah[2][4], fal[2][4];
#pragma unroll
        for (int mt = 0; mt < 2; mt++) {
            uint32_t addr = sm + CKH + (t0 + krow) * 272 + (f0 + mt * 16 + mcol) * 2;
            ldm_x4t(fah[mt], addr);
            ldm_x4t(fal[mt], addr + (CKL - CKH));
        }
        uint32_t fbh[4][2], fbl[4][2];
#pragma unroll
        for (int ntp = 0; ntp < 2; ntp++) {
            uint32_t addr = sm + CVH + (t0 + bt_row) * 144 +
                            (e0 + ntp * 16 + bt_nt * 8) * 2;
            uint32_t t4[4];
            ldm_x4t(t4, addr);
            fbh[2 * ntp][0] = t4[0]; fbh[2 * ntp][1] = t4[1];
            fbh[2 * ntp + 1][0] = t4[2]; fbh[2 * ntp + 1][1] = t4[3];
            ldm_x4t(t4, addr + (CVL - CVH));
            fbl[2 * ntp][0] = t4[0]; fbl[2 * ntp][1] = t4[1];
            fbl[2 * ntp + 1][0] = t4[2]; fbl[2 * ntp + 1][1] = t4[3];
        }
#pragma unroll
        for (int mt = 0; mt < 2; mt++)
#pragma unroll
            for (int nt = 0; nt < 4; nt++) {
                mma16816(acc[mt][nt], fah[mt], fbh[nt]);
                mma16816(acc[mt][nt], fal[mt], fbh[nt]);
                mma16816(acc[mt][nt], fah[mt], fbl[nt]);
            }
    }

    __syncthreads();
    if (tid < 128) {
        const float* zp_ = (const float*)(smem + CZP);
        zc[(size_t)blk * NF + tid] = zp_[tid] + zp_[128 + tid];
    }

    int gid = lane >> 2, tig = lane & 3;
    float* Sbase = Sc + (size_t)blk * NF * HD;
#pragma unroll
    for (int mt = 0; mt < 2; mt++)
#pragma unroll
        for (int nt = 0; nt < 4; nt++)
#pragma unroll
            for (int rh = 0; rh < 2; rh++) {
                int f = f0 + mt * 16 + gid + rh * 8;
                int e = e0 + nt * 8 + tig * 2;
                *(float2*)(Sbase + (size_t)f * HD + e) =
                    make_float2(acc[mt][nt][2 * rh], acc[mt][nt][2 * rh + 1]);
            }
}

// ---------------- exclusive prefix over chunks --------------------------------
__global__ __launch_bounds__(256) void prefix_kernel(float* __restrict__ Sc,
                                                     float* __restrict__ zc) {
    int bh = blockIdx.x;
    int tid = threadIdx.x;
    for (int idx = tid; idx < NF * HD; idx += 256) {
        float run = 0.f;
        float* p = Sc + (size_t)bh * NCH * NF * HD + idx;
        for (int c = 0; c < NCH; c++) {
            float t = p[(size_t)c * NF * HD];
            p[(size_t)c * NF * HD] = run;
            run += t;
        }
    }
    for (int idx = tid; idx < NF; idx += 256) {
        float run = 0.f;
        float* p = zc + (size_t)bh * NCH * NF + idx;
        for (int c = 0; c < NCH; c++) {
            float t = p[c * NF];
            p[c * NF] = run;
            run += t;
        }
    }
}

// ---------------- MMA attention chunk kernel (unchanged from R5) --------------
#define PQE 136
#define PQB (PQE * 2)
#define PVE 72
#define PVB (PVE * 2)
#define OQH 0
#define OQL (OQH + 128 * PQB)
#define OKH (OQL + 128 * PQB)
#define OKL (OKH + 128 * PQB)
#define OVH (OKL + 128 * PQB)
#define OVL (OVH + 128 * PVB)
#define OSH (OVL + 128 * PVB)
#define OSL (OSH + 128 * PVB)
#define ODEN (OSL + 128 * PVB)
#define OZ  (ODEN + 512)
#define ATTN_SMEM (OZ + 512)

__global__ __launch_bounds__(256, 1) void attn_mma_kernel(
    const __nv_bfloat16* __restrict__ qph, const __nv_bfloat16* __restrict__ qpl,
    const __nv_bfloat16* __restrict__ kph, const __nv_bfloat16* __restrict__ kpl,
    const __nv_bfloat16* __restrict__ vh, const __nv_bfloat16* __restrict__ vl,
    const float* __restrict__ Sp, const float* __restrict__ zp,
    __nv_bfloat16* __restrict__ yh, __nv_bfloat16* __restrict__ yl) {
    int blk = blockIdx.x;
    int c = blk % NCH, bh = blk / NCH;
    int b = bh / HH, h = bh % HH;

    extern __shared__ char smem[];
    uint32_t sm = smem_u32(smem);
    int tid = threadIdx.x, lane = tid & 31, wid = tid >> 5;

    {
        size_t base = ((size_t)bh * TT + c * CC) * NF;
        const uint4* sqh = (const uint4*)(qph + base);
        const uint4* sql = (const uint4*)(qpl + base);
        const uint4* skh = (const uint4*)(kph + base);
        const uint4* skl = (const uint4*)(kpl + base);
        for (int i = tid; i < 2048; i += 256) {
            int row = i >> 4, c8 = i & 15;
            int off = row * PQB + c8 * 16;
            *(uint4*)(smem + OQH + off) = sqh[i];
            *(uint4*)(smem + OQL + off) = sql[i];
            *(uint4*)(smem + OKH + off) = skh[i];
            *(uint4*)(smem + OKL + off) = skl[i];
        }
        for (int i = tid; i < 1024; i += 256) {
            int row = i >> 3, c8 = i & 7;
            size_t go = (size_t)(b * TT + c * CC + row) * DM + h * HD + c8 * 8;
            *(uint4*)(smem + OVH + row * PVB + c8 * 16) = *(const uint4*)(vh + go);
            *(uint4*)(smem + OVL + row * PVB + c8 * 16) = *(const uint4*)(vl + go);
        }
        const float4* sS = (const float4*)(Sp + (size_t)blk * NF * HD);
        for (int i = tid; i < 2048; i += 256) {
            int row = i >> 4, c4 = i & 15;
            float4 v = sS[i];
            __nv_bfloat162 l0, l1;
            __nv_bfloat162 h0 = split_pair(v.x, v.y, l0);
            __nv_bfloat162 h1 = split_pair(v.z, v.w, l1);
            uint2 hv, lv;
            hv.x = *(uint32_t*)&h0; hv.y = *(uint32_t*)&h1;
            lv.x = *(uint32_t*)&l0; lv.y = *(uint32_t*)&l1;
            *(uint2*)(smem + OSH + row * PVB + c4 * 8) = hv;
            *(uint2*)(smem + OSL + row * PVB + c4 * 8) = lv;
        }
        const float4* sz = (const float4*)(zp + (size_t)blk * NF);
        for (int i = tid; i < 32; i += 256)
            ((float4*)(smem + OZ))[i] = sz[i];
    }
    __syncthreads();

    int wm = wid & 3, wn = wid >> 2;
    int gid = lane >> 2, tig = lane & 3;
    int a_row = lane & 15, a_koff = (lane >= 16) ? 8 : 0;
    int b_row = (lane & 7) + ((lane >> 4) << 3);
    int b_koff = ((lane >> 3) & 1) * 8;

    float accA[2][8][4];
#pragma unroll
    for (int mt = 0; mt < 2; mt++)
#pragma unroll
        for (int nt = 0; nt < 8; nt++)
#pragma unroll
            for (int i = 0; i < 4; i++) accA[mt][nt][i] = 0.f;

#pragma unroll
    for (int kt = 0; kt < 8; kt++) {
        uint32_t fah[2][4], fal[2][4];
#pragma unroll
        for (int mt = 0; mt < 2; mt++) {
            uint32_t addr = sm + OQH + (wm * 32 + mt * 16 + a_row) * PQB +
                            (kt * 16 + a_koff) * 2;
            ldm_x4(fah[mt], addr);
            ldm_x4(fal[mt], addr + (OQL - OQH));
        }
        uint32_t fbh[8][2], fbl[8][2];
#pragma unroll
        for (int ntp = 0; ntp < 4; ntp++) {
            uint32_t addr = sm + OKH + (wn * 64 + ntp * 16 + b_row) * PQB +
                            (kt * 16 + b_koff) * 2;
            uint32_t t4[4];
            ldm_x4(t4, addr);
            fbh[2 * ntp][0] = t4[0]; fbh[2 * ntp][1] = t4[1];
            fbh[2 * ntp + 1][0] = t4[2]; fbh[2 * ntp + 1][1] = t4[3];
            ldm_x4(t4, addr + (OKL - OKH));
            fbl[2 * ntp][0] = t4[0]; fbl[2 * ntp][1] = t4[1];
            fbl[2 * ntp + 1][0] = t4[2]; fbl[2 * ntp + 1][1] = t4[3];
        }
#pragma unroll
        for (int mt = 0; mt < 2; mt++)
#pragma unroll
            for (int nt = 0; nt < 8; nt++) {
                mma16816(accA[mt][nt], fah[mt], fbh[nt]);
                mma16816(accA[mt][nt], fal[mt], fbh[nt]);
                mma16816(accA[mt][nt], fah[mt], fbl[nt]);
            }
    }
    __syncthreads();

#pragma unroll
    for (int mt = 0; mt < 2; mt++)
#pragma unroll
        for (int nt = 0; nt < 8; nt++)
#pragma unroll
            for (int rh = 0; rh < 2; rh++) {
                int row = wm * 32 + mt * 16 + gid + rh * 8;
                int col = wn * 64 + nt * 8 + tig * 2;
                float c0 = accA[mt][nt][2 * rh], c1 = accA[mt][nt][2 * rh + 1];
                if (col > row) c0 = 0.f;
                if (col + 1 > row) c1 = 0.f;
                __nv_bfloat162 lo;
                __nv_bfloat162 hi = split_pair(c0, c1, lo);
                *(__nv_bfloat162*)(smem + OKH + row * PQB + col * 2) = hi;
                *(__nv_bfloat162*)(smem + OKL + row * PQB + col * 2) = lo;
            }
    __syncthreads();

    if (tid < 128) {
        const __nv_bfloat16* ah_ = (const __nv_bfloat16*)(smem + OKH + tid * PQB);
        const __nv_bfloat16* al_ = (const __nv_bfloat16*)(smem + OKL + tid * PQB);
        const __nv_bfloat16* qh_ = (const __nv_bfloat16*)(smem + OQH + tid * PQB);
        const __nv_bfloat16* ql_ = (const __nv_bfloat16*)(smem + OQL + tid * PQB);
        const float* zf = (const float*)(smem + OZ);
        float s = 0.f;
        for (int j = 0; j < NF; j++)
            s += __bfloat162float(ah_[j]) + __bfloat162float(al_[j]);
        for (int j = 0; j < NF; j++)
            s += (__bfloat162float(qh_[j]) + __bfloat162float(ql_[j])) * zf[j];
        ((float*)(smem + ODEN))[tid] = s;
    }
    __syncthreads();

    float accO[2][4][4];
#pragma unroll
    for (int mt = 0; mt < 2; mt++)
#pragma unroll
        for (int nt = 0; nt < 4; nt++)
#pragma unroll
            for (int i = 0; i < 4; i++) accO[mt][nt][i] = 0.f;

    int bt_row = (lane & 7) + ((lane >> 3) & 1) * 8;
    int bt_nt = lane >> 4;

#pragma unroll
    for (int kt = 0; kt < 16; kt++) {
        int isA = (kt < 8);
        uint32_t abase = isA ? OKH : OQH;
        uint32_t abl = isA ? OKL : OQL;
        uint32_t bbase = isA ? OVH : OSH;
        uint32_t bbl = isA ? OVL : OSL;
        int kk = (kt & 7) * 16;
        uint32_t fah[2][4], fal[2][4];
#pragma unroll
        for (int mt = 0; mt < 2; mt++) {
            uint32_t addr = sm + abase + (wm * 32 + mt * 16 + a_row) * PQB +
                            (kk + a_koff) * 2;
            ldm_x4(fah[mt], addr);
            ldm_x4(fal[mt], addr + (abl - abase));
        }
        uint32_t fbh[4][2], fbl[4][2];
#pragma unroll
        for (int ntp = 0; ntp < 2; ntp++) {
            uint32_t addr = sm + bbase + (kk + bt_row) * PVB +
                            (wn * 32 + ntp * 16 + bt_nt * 8) * 2;
            uint32_t t4[4];
            ldm_x4t(t4, addr);
            fbh[2 * ntp][0] = t4[0]; fbh[2 * ntp][1] = t4[1];
            fbh[2 * ntp + 1][0] = t4[2]; fbh[2 * ntp + 1][1] = t4[3];
            ldm_x4t(t4, addr + (bbl - bbase));
            fbl[2 * ntp][0] = t4[0]; fbl[2 * ntp][1] = t4[1];
            fbl[2 * ntp + 1][0] = t4[2]; fbl[2 * ntp + 1][1] = t4[3];
        }
#pragma unroll
        for (int mt = 0; mt < 2; mt++)
#pragma unroll
            for (int nt = 0; nt < 4; nt++) {
                mma16816(accO[mt][nt], fah[mt], fbh[nt]);
                mma16816(accO[mt][nt], fal[mt], fbh[nt]);
                mma16816(accO[mt][nt], fah[mt], fbl[nt]);
            }
    }

    const float* den = (const float*)(smem + ODEN);
#pragma unroll
    for (int mt = 0; mt < 2; mt++)
#pragma unroll
        for (int nt = 0; nt < 4; nt++)
#pragma unroll
            for (int rh = 0; rh < 2; rh++) {
                int row = wm * 32 + mt * 16 + gid + rh * 8;
                int col = wn * 32 + nt * 8 + tig * 2;
                float inv = 1.0f / (den[row] + EPSV);
                float v0 = accO[mt][nt][2 * rh] * inv;
                float v1 = accO[mt][nt][2 * rh + 1] * inv;
                __nv_bfloat162 lo;
                __nv_bfloat162 hi = split_pair(v0, v1, lo);
                size_t go = (size_t)(b * TT + c * CC + row) * DM + h * HD + col;
                *(__nv_bfloat162*)(yh + go) = hi;
                *(__nv_bfloat162*)(yl + go) = lo;
            }
}

// ---------------- launcher ----------------------------------------------------
extern "C" void kernel_launch(void* const* d_in, const int* in_sizes, int n_in,
                              void* d_out, int out_size) {
    const float* x  = (const float*)d_in[0];
    const float* Wq = (const float*)d_in[1];
    const float* Wk = (const float*)d_in[2];
    const float* Wv = (const float*)d_in[3];
    const float* Wo = (const float*)d_in[4];
    const float* Wf = (const float*)d_in[5];
    float* out = (float*)d_out;

    float *pq, *pk, *pS, *pz;
    __nv_bfloat16 *pxh, *pxl, *pvh, *pvl, *pyh, *pyl, *pwh, *pwl;
    __nv_bfloat16 *pqph, *pqpl, *pkph, *pkpl;
    cudaGetSymbolAddress((void**)&pq,  g_q);
    cudaGetSymbolAddress((void**)&pk,  g_k);
    cudaGetSymbolAddress((void**)&pS,  g_S);
    cudaGetSymbolAddress((void**)&pz,  g_z);
    cudaGetSymbolAddress((void**)&pxh, g_xh);
    cudaGetSymbolAddress((void**)&pxl, g_xl);
    cudaGetSymbolAddress((void**)&pvh, g_vh);
    cudaGetSymbolAddress((void**)&pvl, g_vl);
    cudaGetSymbolAddress((void**)&pyh, g_yh);
    cudaGetSymbolAddress((void**)&pyl, g_yl);
    cudaGetSymbolAddress((void**)&pwh, g_wh);
    cudaGetSymbolAddress((void**)&pwl, g_wl);
    cudaGetSymbolAddress((void**)&pqph, g_qph);
    cudaGetSymbolAddress((void**)&pqpl, g_qpl);
    cudaGetSymbolAddress((void**)&pkph, g_kph);
    cudaGetSymbolAddress((void**)&pkpl, g_kpl);

    cudaFuncSetAttribute(gemm_big<0>, cudaFuncAttributeMaxDynamicSharedMemorySize, BSMEM);
    cudaFuncSetAttribute(gemm_big<1>, cudaFuncAttributeMaxDynamicSharedMemorySize, BSMEM);
    cudaFuncSetAttribute(feature_mma_kernel, cudaFuncAttributeMaxDynamicSharedMemorySize, FSMEM);
    cudaFuncSetAttribute(chunk_kv_mma, cudaFuncAttributeMaxDynamicSharedMemorySize, CSMEM);
    cudaFuncSetAttribute(attn_mma_kernel, cudaFuncAttributeMaxDynamicSharedMemorySize, ATTN_SMEM);

    // 1. split x
    split_kernel<<<2048, 256>>>(x, pxh, pxl, ROWS * DM / 4);
    // 2. transpose + split weights into [4096,1024]
    dim3 wg(DM / 32, DM / 32);
    wsplit_kernel<<<wg, 256>>>(Wq, pwh + 0 * (size_t)DM * DM, pwl + 0 * (size_t)DM * DM);
    wsplit_kernel<<<wg, 256>>>(Wk, pwh + 1 * (size_t)DM * DM, pwl + 1 * (size_t)DM * DM);
    wsplit_kernel<<<wg, 256>>>(Wv, pwh + 2 * (size_t)DM * DM, pwl + 2 * (size_t)DM * DM);
    wsplit_kernel<<<wg, 256>>>(Wo, pwh + 3 * (size_t)DM * DM, pwl + 3 * (size_t)DM * DM);

    // 3. fused QKV projection (N = 3072)
    gemm_big<1><<<dim3(12, ROWS / BGM), 256, BSMEM>>>(pxh, pxl, pwh, pwl,
                                                      pq, pk, pvh, pvl);

    // 4. feature map + attention
    feature_mma_kernel<<<dim3(BHT / 128, 2), 256, FSMEM>>>(pq, pk, Wf,
                                                           pqph, pqpl, pkph, pkpl);
    chunk_kv_mma<<<BB * HH * NCH, 256, CSMEM>>>(pkph, pkpl, pvh, pvl, pS, pz);
    prefix_kernel<<<BB * HH, 256>>>(pS, pz);
    attn_mma_kernel<<<BB * HH * NCH, 256, ATTN_SMEM>>>(pqph, pqpl, pkph, pkpl,
                                                       pvh, pvl, pS, pz, pyh, pyl);

    // 5. output projection (N = 1024)
    gemm_big<0><<<dim3(4, ROWS / BGM), 256, BSMEM>>>(
        pyh, pyl, pwh + 3 * (size_t)DM * DM, pwl + 3 * (size_t)DM * DM,
        out, nullptr, nullptr, nullptr);
}

// round 14
// speedup vs baseline: 2.7675x; 1.0274x over previous
#include <cuda_runtime.h>
#include <cuda_bf16.h>
#include <math.h>
#include <stdint.h>

// Problem constants
#define BB   4
#define TT   2048
#define DM   1024
#define HH   16
#define HD   64
#define NF   128
#define CC   128
#define NCH  (TT/CC)          // 16
#define ROWS (BB*TT)          // 8192
#define BHT  (BB*HH*TT)       // 131072
#define EPSV 1e-6f
#define INV_SQRT_NF 0.08838834764831845f

// ---------------- scratch (device globals) ------------------------------------
__device__ float g_q [ROWS*DM];
__device__ float g_k [ROWS*DM];
__device__ float g_S [(size_t)BB*HH*NCH*NF*HD];
__device__ float g_z [(size_t)BB*HH*NCH*NF];
__device__ __nv_bfloat16 g_xh[ROWS*DM];
__device__ __nv_bfloat16 g_xl[ROWS*DM];
__device__ __nv_bfloat16 g_vh[ROWS*DM];
__device__ __nv_bfloat16 g_vl[ROWS*DM];
__device__ __nv_bfloat16 g_yh[ROWS*DM];
__device__ __nv_bfloat16 g_yl[ROWS*DM];
__device__ __nv_bfloat16 g_qph[(size_t)BHT*NF];
__device__ __nv_bfloat16 g_qpl[(size_t)BHT*NF];
__device__ __nv_bfloat16 g_kph[(size_t)BHT*NF];
__device__ __nv_bfloat16 g_kpl[(size_t)BHT*NF];
__device__ __nv_bfloat16 g_wh[4*DM*DM];   // transposed weights hi [4096,1024]
__device__ __nv_bfloat16 g_wl[4*DM*DM];   // transposed weights lo

// ======================= PTX helpers ==========================================
__device__ __forceinline__ uint32_t smem_u32(const void* p) {
    uint32_t a;
    asm("{ .reg .u64 t; cvta.to.shared.u64 t, %1; cvt.u32.u64 %0, t; }"
        : "=r"(a) : "l"(p));
    return a;
}
__device__ __forceinline__ void cp16(uint32_t d, const void* g) {
    asm volatile("cp.async.cg.shared.global [%0], [%1], 16;" :: "r"(d), "l"(g));
}
__device__ __forceinline__ void ldm_x4(uint32_t* r, uint32_t a) {
    asm volatile("ldmatrix.sync.aligned.m8n8.x4.shared.b16 {%0,%1,%2,%3}, [%4];"
                 : "=r"(r[0]), "=r"(r[1]), "=r"(r[2]), "=r"(r[3]) : "r"(a));
}
__device__ __forceinline__ void ldm_x4t(uint32_t* r, uint32_t a) {
    asm volatile("ldmatrix.sync.aligned.m8n8.x4.trans.shared.b16 {%0,%1,%2,%3}, [%4];"
                 : "=r"(r[0]), "=r"(r[1]), "=r"(r[2]), "=r"(r[3]) : "r"(a));
}
__device__ __forceinline__ void mma16816(float* c, const uint32_t* a, const uint32_t* b) {
    asm volatile(
        "mma.sync.aligned.m16n8k16.row.col.f32.bf16.bf16.f32 "
        "{%0,%1,%2,%3}, {%4,%5,%6,%7}, {%8,%9}, {%0,%1,%2,%3};"
        : "+f"(c[0]), "+f"(c[1]), "+f"(c[2]), "+f"(c[3])
        : "r"(a[0]), "r"(a[1]), "r"(a[2]), "r"(a[3]), "r"(b[0]), "r"(b[1]));
}
__device__ __forceinline__ __nv_bfloat162 split_pair(float a, float b,
                                                     __nv_bfloat162& lo) {
    __nv_bfloat16 h0 = __float2bfloat16(a);
    __nv_bfloat16 h1 = __float2bfloat16(b);
    __nv_bfloat16 l0 = __float2bfloat16(a - __bfloat162float(h0));
    __nv_bfloat16 l1 = __float2bfloat16(b - __bfloat162float(h1));
    lo.x = l0; lo.y = l1;
    __nv_bfloat162 hi; hi.x = h0; hi.y = h1;
    return hi;
}

// ======================= bf16 split / transpose ===============================
__global__ __launch_bounds__(256) void split_kernel(const float* __restrict__ x,
                                                    __nv_bfloat16* __restrict__ h,
                                                    __nv_bfloat16* __restrict__ l,
                                                    int n4) {
    int i = blockIdx.x * blockDim.x + threadIdx.x;
    int stride = gridDim.x * blockDim.x;
    for (; i < n4; i += stride) {
        float4 v = ((const float4*)x)[i];
        __nv_bfloat162 la, lb;
        __nv_bfloat162 ha = split_pair(v.x, v.y, la);
        __nv_bfloat162 hb = split_pair(v.z, v.w, lb);
        ((__nv_bfloat162*)h)[2 * i]     = ha;
        ((__nv_bfloat162*)h)[2 * i + 1] = hb;
        ((__nv_bfloat162*)l)[2 * i]     = la;
        ((__nv_bfloat162*)l)[2 * i + 1] = lb;
    }
}

// All four weights in one launch, blockIdx.z selects matrix.
__global__ __launch_bounds__(256) void wsplit4_kernel(
    const float* __restrict__ W0, const float* __restrict__ W1,
    const float* __restrict__ W2, const float* __restrict__ W3,
    __nv_bfloat16* __restrict__ th, __nv_bfloat16* __restrict__ tl) {
    __shared__ float t[32][33];
    int z = blockIdx.z;
    const float* W = (z == 0) ? W0 : (z == 1) ? W1 : (z == 2) ? W2 : W3;
    th += (size_t)z * DM * DM;
    tl += (size_t)z * DM * DM;
    int bn = blockIdx.x * 32, bk = blockIdx.y * 32;
    int tx = threadIdx.x & 31, ty = threadIdx.x >> 5;
    for (int r = ty; r < 32; r += 8)
        t[r][tx] = W[(size_t)(bk + r) * DM + bn + tx];
    __syncthreads();
    for (int r = ty; r < 32; r += 8) {
        float v = t[tx][r];
        __nv_bfloat16 h = __float2bfloat16(v);
        __nv_bfloat16 l = __float2bfloat16(v - __bfloat162float(h));
        th[(size_t)(bn + r) * DM + bk + tx] = h;
        tl[(size_t)(bn + r) * DM + bk + tx] = l;
    }
}

// ======================= big-tile mma.sync bf16x3 GEMM ========================
// Block tile 128x256x32, 16 warps (4M x 4N), warp tile 32x64, 3 stages.
#define BGM 128
#define BGN 256
#define BGK 32
#define BNK (DM / BGK)            // 32
#define BROWB 80
#define BSA_H 0
#define BSA_L (128 * BROWB)       // 10240
#define BSB_H (2 * 128 * BROWB)   // 20480
#define BSB_L (BSB_H + 256 * BROWB)
#define BSTAGE_B (BSB_L + 256 * BROWB)   // 61440
#define BSMEM (3 * BSTAGE_B)             // 184320

__device__ __forceinline__ void bload_stage(uint32_t sbase, int tid,
                                            const __nv_bfloat16* ah,
                                            const __nv_bfloat16* al,
                                            const __nv_bfloat16* bh,
                                            const __nv_bfloat16* bl, int k0) {
    int r0 = tid >> 2, ch = tid & 3;   // r0 0..127
    cp16(sbase + BSA_H + r0 * BROWB + ch * 16, ah + (size_t)r0 * DM + k0 + ch * 8);
    cp16(sbase + BSA_L + r0 * BROWB + ch * 16, al + (size_t)r0 * DM + k0 + ch * 8);
#pragma unroll
    for (int j = 0; j < 4; j++) {
        const __nv_bfloat16* base = (j < 2) ? bh : bl;
        int r = (j & 1) * 128 + r0;
        cp16(sbase + ((j < 2) ? BSB_H : BSB_L) + r * BROWB + ch * 16,
             base + (size_t)r * DM + k0 + ch * 8);
    }
}

// MODE 0: all columns fp32 -> Cq.   MODE 1: QKV mixed (q,k fp32; v bf16 h/l).
template <int MODE>
__global__ __launch_bounds__(512, 1) void gemm_big(
    const __nv_bfloat16* __restrict__ Ah, const __nv_bfloat16* __restrict__ Al,
    const __nv_bfloat16* __restrict__ Bh, const __nv_bfloat16* __restrict__ Bl,
    float* __restrict__ Cq, float* __restrict__ Ck,
    __nv_bfloat16* __restrict__ Cvh, __nv_bfloat16* __restrict__ Cvl) {
    extern __shared__ char smem[];
    uint32_t sm = smem_u32(smem);
    int tid = threadIdx.x, lane = tid & 31, wid = tid >> 5;
    int wm = wid & 3, wn = wid >> 2;   // 4x4 warps, warp tile 32x64
    int bm = blockIdx.y * BGM, bn = blockIdx.x * BGN;

    const __nv_bfloat16* pAh = Ah + (size_t)bm * DM;
    const __nv_bfloat16* pAl = Al + (size_t)bm * DM;
    const __nv_bfloat16* pBh = Bh + (size_t)bn * DM;
    const __nv_bfloat16* pBl = Bl + (size_t)bn * DM;

    float acc[2][8][4];
#pragma unroll
    for (int mt = 0; mt < 2; mt++)
#pragma unroll
        for (int nt = 0; nt < 8; nt++)
#pragma unroll
            for (int i = 0; i < 4; i++) acc[mt][nt][i] = 0.f;

#pragma unroll
    for (int s = 0; s < 2; s++) {
        bload_stage(sm + s * BSTAGE_B, tid, pAh, pAl, pBh, pBl, s * BGK);
        asm volatile("cp.async.commit_group;");
    }

    int a_row = lane & 15;
    int a_koff = (lane >= 16) ? 8 : 0;
    int b_row = (lane & 7) + ((lane >> 4) << 3);
    int b_koff = ((lane >> 3) & 1) * 8;

    for (int kt = 0; kt < BNK; kt++) {
        asm volatile("cp.async.wait_group 1;");
        __syncthreads();
        int pf = kt + 2;
        if (pf < BNK)
            bload_stage(sm + (pf % 3) * BSTAGE_B, tid, pAh, pAl, pBh, pBl,
                        pf * BGK);
        asm volatile("cp.async.commit_group;");

        uint32_t sb = sm + (kt % 3) * BSTAGE_B;
#pragma unroll
        for (int k16 = 0; k16 < 2; k16++) {
            uint32_t fah[2][4], fal[2][4];
#pragma unroll
            for (int mt = 0; mt < 2; mt++) {
                uint32_t addr = sb + BSA_H + (wm * 32 + mt * 16 + a_row) * BROWB +
                                (k16 * 16 + a_koff) * 2;
                ldm_x4(fah[mt], addr);
                ldm_x4(fal[mt], addr + (BSA_L - BSA_H));
            }
#pragma unroll
            for (int half = 0; half < 2; half++) {
                uint32_t fbh[4][2], fbl[4][2];
#pragma unroll
                for (int ntp = 0; ntp < 2; ntp++) {
                    uint32_t addr = sb + BSB_H +
                                    (wn * 64 + half * 32 + ntp * 16 + b_row) * BROWB +
                                    (k16 * 16 + b_koff) * 2;
                    uint32_t t4[4];
                    ldm_x4(t4, addr);
                    fbh[2 * ntp][0] = t4[0]; fbh[2 * ntp][1] = t4[1];
                    fbh[2 * ntp + 1][0] = t4[2]; fbh[2 * ntp + 1][1] = t4[3];
                    ldm_x4(t4, addr + (BSB_L - BSB_H));
                    fbl[2 * ntp][0] = t4[0]; fbl[2 * ntp][1] = t4[1];
                    fbl[2 * ntp + 1][0] = t4[2]; fbl[2 * ntp + 1][1] = t4[3];
                }
#pragma unroll
                for (int mt = 0; mt < 2; mt++)
#pragma unroll
                    for (int n4 = 0; n4 < 4; n4++) {
                        float* a4 = acc[mt][half * 4 + n4];
                        mma16816(a4, fah[mt], fbh[n4]);
                        mma16816(a4, fal[mt], fbh[n4]);
                        mma16816(a4, fah[mt], fbl[n4]);
                    }
            }
        }
    }

    int gid = lane >> 2, tig = lane & 3;
#pragma unroll
    for (int mt = 0; mt < 2; mt++) {
#pragma unroll
        for (int nt = 0; nt < 8; nt++) {
#pragma unroll
            for (int rh = 0; rh < 2; rh++) {
                int row = bm + wm * 32 + mt * 16 + gid + rh * 8;
                int colg = bn + wn * 64 + nt * 8 + tig * 2;
                float c0 = acc[mt][nt][2 * rh], c1 = acc[mt][nt][2 * rh + 1];
                if (MODE == 0) {
                    *(float2*)(Cq + (size_t)row * DM + colg) = make_float2(c0, c1);
                } else {
                    int region = colg >> 10, cl = colg & 1023;
                    if (region == 0) {
                        *(float2*)(Cq + (size_t)row * DM + cl) = make_float2(c0, c1);
                    } else if (region == 1) {
                        *(float2*)(Ck + (size_t)row * DM + cl) = make_float2(c0, c1);
                    } else {
                        __nv_bfloat162 lo;
                        __nv_bfloat162 hi = split_pair(c0, c1, lo);
                        *(__nv_bfloat162*)(Cvh + (size_t)row * DM + cl) = hi;
                        *(__nv_bfloat162*)(Cvl + (size_t)row * DM + cl) = lo;
                    }
                }
            }
        }
    }
}

// ---------------- FAVOR+ feature map via MMA ----------------------------------
#define FQF 0
#define FQH 34816
#define FQL (FQH + 18432)
#define FWH (FQL + 18432)
#define FWL (FWH + 18432)
#define FSQ (FWL + 18432)
#define FSMEM (FSQ + 512)

__global__ __launch_bounds__(256, 1) void feature_mma_kernel(
    const float* __restrict__ q, const float* __restrict__ k,
    const float* __restrict__ Wf,
    __nv_bfloat16* __restrict__ qph, __nv_bfloat16* __restrict__ qpl,
    __nv_bfloat16* __restrict__ kph, __nv_bfloat16* __restrict__ kpl) {
    const float* src = blockIdx.y ? k : q;
    __nv_bfloat16* dh = blockIdx.y ? kph : qph;
    __nv_bfloat16* dl = blockIdx.y ? kpl : qpl;

    extern __shared__ char smem[];
    uint32_t sm = smem_u32(smem);
    int tid = threadIdx.x, lane = tid & 31, wid = tid >> 5;
    int row0 = blockIdx.x * 128;
    int bh = row0 / TT, t0 = row0 % TT;
    int b = bh >> 4, h = bh & 15;

    float* qf = (float*)(smem + FQF);       // [128][68]
    const float* base = src + ((size_t)(b * TT + t0)) * DM + h * HD;
    for (int i = tid; i < 2048; i += 256) {
        int r = i >> 4, c4 = i & 15;
        *(float4*)(qf + r * 68 + c4 * 4) = *(const float4*)(base + (size_t)r * DM + c4 * 4);
    }
    for (int i = tid; i < 8192; i += 256) {
        int d = i >> 7, f = i & 127;
        float v = Wf[i];
        __nv_bfloat16 h16 = __float2bfloat16(v);
        __nv_bfloat16 l16 = __float2bfloat16(v - __bfloat162float(h16));
        ((__nv_bfloat16*)(smem + FWH))[f * 72 + d] = h16;
        ((__nv_bfloat16*)(smem + FWL))[f * 72 + d] = l16;
    }
    __syncthreads();
    if (tid < 128) {
        float s = 0.f;
        const float4* qr = (const float4*)(qf + tid * 68);
#pragma unroll
        for (int j = 0; j < 16; j++) {
            float4 v = qr[j];
            s += v.x * v.x + v.y * v.y + v.z * v.z + v.w * v.w;
        }
        ((float*)(smem + FSQ))[tid] = 0.5f * s;
    }
    for (int i = tid; i < 4096; i += 256) {
        int r = i >> 5, c2 = i & 31;
        float2 v = *(float2*)(qf + r * 68 + c2 * 2);
        __nv_bfloat162 lo;
        __nv_bfloat162 hi = split_pair(v.x, v.y, lo);
        *(__nv_bfloat162*)(smem + FQH + r * 144 + c2 * 4) = hi;
        *(__nv_bfloat162*)(smem + FQL + r * 144 + c2 * 4) = lo;
    }
    __syncthreads();

    int wm = wid & 3, wn = wid >> 2;
    int a_row = lane & 15, a_koff = (lane >= 16) ? 8 : 0;
    int b_row = (lane & 7) + ((lane >> 4) << 3);
    int b_koff = ((lane >> 3) & 1) * 8;

    float acc[2][8][4];
#pragma unroll
    for (int mt = 0; mt < 2; mt++)
#pragma unroll
        for (int nt = 0; nt < 8; nt++)
#pragma unroll
            for (int i = 0; i < 4; i++) acc[mt][nt][i] = 0.f;

#pragma unroll
    for (int kt = 0; kt < 4; kt++) {
        uint32_t fah[2][4], fal[2][4];
#pragma unroll
        for (int mt = 0; mt < 2; mt++) {
            uint32_t addr = sm + FQH + (wm * 32 + mt * 16 + a_row) * 144 +
                            (kt * 16 + a_koff) * 2;
            ldm_x4(fah[mt], addr);
            ldm_x4(fal[mt], addr + (FQL - FQH));
        }
        uint32_t fbh[8][2], fbl[8][2];
#pragma unroll
        for (int ntp = 0; ntp < 4; ntp++) {
            uint32_t addr = sm + FWH + (wn * 64 + ntp * 16 + b_row) * 144 +
                            (kt * 16 + b_koff) * 2;
            uint32_t t4[4];
            ldm_x4(t4, addr);
            fbh[2 * ntp][0] = t4[0]; fbh[2 * ntp][1] = t4[1];
            fbh[2 * ntp + 1][0] = t4[2]; fbh[2 * ntp + 1][1] = t4[3];
            ldm_x4(t4, addr + (FWL - FWH));
            fbl[2 * ntp][0] = t4[0]; fbl[2 * ntp][1] = t4[1];
            fbl[2 * ntp + 1][0] = t4[2]; fbl[2 * ntp + 1][1] = t4[3];
        }
#pragma unroll
        for (int mt = 0; mt < 2; mt++)
#pragma unroll
            for (int nt = 0; nt < 8; nt++) {
                mma16816(acc[mt][nt], fah[mt], fbh[nt]);
                mma16816(acc[mt][nt], fal[mt], fbh[nt]);
                mma16816(acc[mt][nt], fah[mt], fbl[nt]);
            }
    }

    const float* sq = (const float*)(smem + FSQ);
    int gid = lane >> 2, tig = lane & 3;
#pragma unroll
    for (int mt = 0; mt < 2; mt++)
#pragma unroll
        for (int nt = 0; nt < 8; nt++)
#pragma unroll
            for (int rh = 0; rh < 2; rh++) {
                int row = wm * 32 + mt * 16 + gid + rh * 8;
                int f = wn * 64 + nt * 8 + tig * 2;
                float s = sq[row];
                float v0 = expf(acc[mt][nt][2 * rh] - s) * INV_SQRT_NF;
                float v1 = expf(acc[mt][nt][2 * rh + 1] - s) * INV_SQRT_NF;
                __nv_bfloat162 lo;
                __nv_bfloat162 hi = split_pair(v0, v1, lo);
                size_t o = (size_t)(row0 + row) * NF + f;
                *(__nv_bfloat162*)(dh + o) = hi;
                *(__nv_bfloat162*)(dl + o) = lo;
            }
}

// ---------------- per-chunk K^T V via MMA -------------------------------------
#define CKH 0
#define CKL 34816
#define CVH 69632
#define CVL (CVH + 18432)
#define CZP (CVL + 18432)
#define CSMEM (CZP + 1024)

__global__ __launch_bounds__(256, 1) void chunk_kv_mma(
    const __nv_bfloat16* __restrict__ kph, const __nv_bfloat16* __restrict__ kpl,
    const __nv_bfloat16* __restrict__ vh, const __nv_bfloat16* __restrict__ vl,
    float* __restrict__ Sc, float* __restrict__ zc) {
    int blk = blockIdx.x;
    int c = blk % NCH, bh = blk / NCH;
    int b = bh / HH, h = bh % HH;

    extern __shared__ char smem[];
    uint32_t sm = smem_u32(smem);
    int tid = threadIdx.x, lane = tid & 31, wid = tid >> 5;

    size_t gbase = ((size_t)bh * TT + c * CC) * NF;
    for (int i = tid; i < 2048; i += 256) {
        int r = i >> 4, c8 = i & 15;
        *(uint4*)(smem + CKH + r * 272 + c8 * 16) = ((const uint4*)(kph + gbase))[i];
        *(uint4*)(smem + CKL + r * 272 + c8 * 16) = ((const uint4*)(kpl + gbase))[i];
    }
    for (int i = tid; i < 1024; i += 256) {
        int r = i >> 3, c8 = i & 7;
        size_t go = (size_t)(b * TT + c * CC + r) * DM + h * HD + c8 * 8;
        *(uint4*)(smem + CVH + r * 144 + c8 * 16) = *(const uint4*)(vh + go);
        *(uint4*)(smem + CVL + r * 144 + c8 * 16) = *(const uint4*)(vl + go);
    }
    __syncthreads();

    {
        int f = tid & 127, half = tid >> 7;
        float s = 0.f;
        const __nv_bfloat16* kh_ = (const __nv_bfloat16*)(smem + CKH);
        const __nv_bfloat16* kl_ = (const __nv_bfloat16*)(smem + CKL);
        for (int t = half * 64; t < half * 64 + 64; t++)
            s += __bfloat162float(kh_[t * 136 + f]) + __bfloat162float(kl_[t * 136 + f]);
        ((float*)(smem + CZP))[half * 128 + f] = s;
    }

    int wm = wid & 3, wn = (wid >> 2) & 1;
    int f0 = wm * 32, e0 = wn * 32;
    int r7 = lane & 7, oct = lane >> 3;
    int krow = r7 + ((oct >> 1) & 1) * 8;
    int mcol = (oct & 1) * 8;
    int bt_row = (lane & 7) + ((lane >> 3) & 1) * 8;
    int bt_nt = lane >> 4;

    float acc[2][4][4];
#pragma unroll
    for (int mt = 0; mt < 2; mt++)
#pragma unroll
        for (int nt = 0; nt < 4; nt++)
#pragma unroll
            for (int i = 0; i < 4; i++) acc[mt][nt][i] = 0.f;

#pragma unroll
    for (int kt = 0; kt < 8; kt++) {
        int t0 = kt * 16;
        uint32_t fah[2][4], fal[2][4];
#pragma unroll
        for (int mt = 0; mt < 2; mt++) {
            uint32_t addr = sm + CKH + (t0 + krow) * 272 + (f0 + mt * 16 + mcol) * 2;
            ldm_x4t(fah[mt], addr);
            ldm_x4t(fal[mt], addr + (CKL - CKH));
        }
        uint32_t fbh[4][2], fbl[4][2];
#pragma unroll
        for (int ntp = 0; ntp < 2; ntp++) {
            uint32_t addr = sm + CVH + (t0 + bt_row) * 144 +
                            (e0 + ntp * 16 + bt_nt * 8) * 2;
            uint32_t t4[4];
            ldm_x4t(t4, addr);
            fbh[2 * ntp][0] = t4[0]; fbh[2 * ntp][1] = t4[1];
            fbh[2 * ntp + 1][0] = t4[2]; fbh[2 * ntp + 1][1] = t4[3];
            ldm_x4t(t4, addr + (CVL - CVH));
            fbl[2 * ntp][0] = t4[0]; fbl[2 * ntp][1] = t4[1];
            fbl[2 * ntp + 1][0] = t4[2]; fbl[2 * ntp + 1][1] = t4[3];
        }
#pragma unroll
        for (int mt = 0; mt < 2; mt++)
#pragma unroll
            for (int nt = 0; nt < 4; nt++) {
                mma16816(acc[mt][nt], fah[mt], fbh[nt]);
                mma16816(acc[mt][nt], fal[mt], fbh[nt]);
                mma16816(acc[mt][nt], fah[mt], fbl[nt]);
            }
    }

    __syncthreads();
    if (tid < 128) {
        const float* zp_ = (const float*)(smem + CZP);
        zc[(size_t)blk * NF + tid] = zp_[tid] + zp_[128 + tid];
    }

    int gid = lane >> 2, tig = lane & 3;
    float* Sbase = Sc + (size_t)blk * NF * HD;
#pragma unroll
    for (int mt = 0; mt < 2; mt++)
#pragma unroll
        for (int nt = 0; nt < 4; nt++)
#pragma unroll
            for (int rh = 0; rh < 2; rh++) {
                int f = f0 + mt * 16 + gid + rh * 8;
                int e = e0 + nt * 8 + tig * 2;
                *(float2*)(Sbase + (size_t)f * HD + e) =
                    make_float2(acc[mt][nt][2 * rh], acc[mt][nt][2 * rh + 1]);
            }
}

// ---------------- exclusive prefix over chunks --------------------------------
__global__ __launch_bounds__(256) void prefix_kernel(float* __restrict__ Sc,
                                                     float* __restrict__ zc) {
    int bh = blockIdx.x;
    int quarter = blockIdx.y;
    int tid = threadIdx.x;
    int lo = quarter * (NF * HD / 4), hi = lo + (NF * HD / 4);
    for (int idx = lo + tid; idx < hi; idx += 256) {
        float run = 0.f;
        float* p = Sc + (size_t)bh * NCH * NF * HD + idx;
        for (int c = 0; c < NCH; c++) {
            float t = p[(size_t)c * NF * HD];
            p[(size_t)c * NF * HD] = run;
            run += t;
        }
    }
    if (quarter == 0) {
        for (int idx = tid; idx < NF; idx += 256) {
            float run = 0.f;
            float* p = zc + (size_t)bh * NCH * NF + idx;
            for (int c = 0; c < NCH; c++) {
                float t = p[c * NF];
                p[c * NF] = run;
                run += t;
            }
        }
    }
}

// ---------------- MMA attention chunk kernel ----------------------------------
#define PQE 136
#define PQB (PQE * 2)
#define PVE 72
#define PVB (PVE * 2)
#define OQH 0
#define OQL (OQH + 128 * PQB)
#define OKH (OQL + 128 * PQB)
#define OKL (OKH + 128 * PQB)
#define OVH (OKL + 128 * PQB)
#define OVL (OVH + 128 * PVB)
#define OSH (OVL + 128 * PVB)
#define OSL (OSH + 128 * PVB)
#define ODEN (OSL + 128 * PVB)
#define OZ  (ODEN + 512)
#define ATTN_SMEM (OZ + 512)

__global__ __launch_bounds__(256, 1) void attn_mma_kernel(
    const __nv_bfloat16* __restrict__ qph, const __nv_bfloat16* __restrict__ qpl,
    const __nv_bfloat16* __restrict__ kph, const __nv_bfloat16* __restrict__ kpl,
    const __nv_bfloat16* __restrict__ vh, const __nv_bfloat16* __restrict__ vl,
    const float* __restrict__ Sp, const float* __restrict__ zp,
    __nv_bfloat16* __restrict__ yh, __nv_bfloat16* __restrict__ yl) {
    int blk = blockIdx.x;
    int c = blk % NCH, bh = blk / NCH;
    int b = bh / HH, h = bh % HH;

    extern __shared__ char smem[];
    uint32_t sm = smem_u32(smem);
    int tid = threadIdx.x, lane = tid & 31, wid = tid >> 5;

    {
        size_t base = ((size_t)bh * TT + c * CC) * NF;
        const uint4* sqh = (const uint4*)(qph + base);
        const uint4* sql = (const uint4*)(qpl + base);
        const uint4* skh = (const uint4*)(kph + base);
        const uint4* skl = (const uint4*)(kpl + base);
        for (int i = tid; i < 2048; i += 256) {
            int row = i >> 4, c8 = i & 15;
            int off = row * PQB + c8 * 16;
            *(uint4*)(smem + OQH + off) = sqh[i];
            *(uint4*)(smem + OQL + off) = sql[i];
            *(uint4*)(smem + OKH + off) = skh[i];
            *(uint4*)(smem + OKL + off) = skl[i];
        }
        for (int i = tid; i < 1024; i += 256) {
            int row = i >> 3, c8 = i & 7;
            size_t go = (size_t)(b * TT + c * CC + row) * DM + h * HD + c8 * 8;
            *(uint4*)(smem + OVH + row * PVB + c8 * 16) = *(const uint4*)(vh + go);
            *(uint4*)(smem + OVL + row * PVB + c8 * 16) = *(const uint4*)(vl + go);
        }
        const float4* sS = (const float4*)(Sp + (size_t)blk * NF * HD);
        for (int i = tid; i < 2048; i += 256) {
            int row = i >> 4, c4 = i & 15;
            float4 v = sS[i];
            __nv_bfloat162 l0, l1;
            __nv_bfloat162 h0 = split_pair(v.x, v.y, l0);
            __nv_bfloat162 h1 = split_pair(v.z, v.w, l1);
            uint2 hv, lv;
            hv.x = *(uint32_t*)&h0; hv.y = *(uint32_t*)&h1;
            lv.x = *(uint32_t*)&l0; lv.y = *(uint32_t*)&l1;
            *(uint2*)(smem + OSH + row * PVB + c4 * 8) = hv;
            *(uint2*)(smem + OSL + row * PVB + c4 * 8) = lv;
        }
        const float4* sz = (const float4*)(zp + (size_t)blk * NF);
        for (int i = tid; i < 32; i += 256)
            ((float4*)(smem + OZ))[i] = sz[i];
    }
    __syncthreads();

    int wm = wid & 3, wn = wid >> 2;
    int gid = lane >> 2, tig = lane & 3;
    int a_row = lane & 15, a_koff = (lane >= 16) ? 8 : 0;
    int b_row = (lane & 7) + ((lane >> 4) << 3);
    int b_koff = ((lane >> 3) & 1) * 8;

    float accA[2][8][4];
#pragma unroll
    for (int mt = 0; mt < 2; mt++)
#pragma unroll
        for (int nt = 0; nt < 8; nt++)
#pragma unroll
            for (int i = 0; i < 4; i++) accA[mt][nt][i] = 0.f;

#pragma unroll
    for (int kt = 0; kt < 8; kt++) {
        uint32_t fah[2][4], fal[2][4];
#pragma unroll
        for (int mt = 0; mt < 2; mt++) {
            uint32_t addr = sm + OQH + (wm * 32 + mt * 16 + a_row) * PQB +
                            (kt * 16 + a_koff) * 2;
            ldm_x4(fah[mt], addr);
            ldm_x4(fal[mt], addr + (OQL - OQH));
        }
        uint32_t fbh[8][2], fbl[8][2];
#pragma unroll
        for (int ntp = 0; ntp < 4; ntp++) {
            uint32_t addr = sm + OKH + (wn * 64 + ntp * 16 + b_row) * PQB +
                            (kt * 16 + b_koff) * 2;
            uint32_t t4[4];
            ldm_x4(t4, addr);
            fbh[2 * ntp][0] = t4[0]; fbh[2 * ntp][1] = t4[1];
            fbh[2 * ntp + 1][0] = t4[2]; fbh[2 * ntp + 1][1] = t4[3];
            ldm_x4(t4, addr + (OKL - OKH));
            fbl[2 * ntp][0] = t4[0]; fbl[2 * ntp][1] = t4[1];
            fbl[2 * ntp + 1][0] = t4[2]; fbl[2 * ntp + 1][1] = t4[3];
        }
#pragma unroll
        for (int mt = 0; mt < 2; mt++)
#pragma unroll
            for (int nt = 0; nt < 8; nt++) {
                mma16816(accA[mt][nt], fah[mt], fbh[nt]);
                mma16816(accA[mt][nt], fal[mt], fbh[nt]);
                mma16816(accA[mt][nt], fah[mt], fbl[nt]);
            }
    }
    __syncthreads();

#pragma unroll
    for (int mt = 0; mt < 2; mt++)
#pragma unroll
        for (int nt = 0; nt < 8; nt++)
#pragma unroll
            for (int rh = 0; rh < 2; rh++) {
                int row = wm * 32 + mt * 16 + gid + rh * 8;
                int col = wn * 64 + nt * 8 + tig * 2;
                float c0 = accA[mt][nt][2 * rh], c1 = accA[mt][nt][2 * rh + 1];
                if (col > row) c0 = 0.f;
                if (col + 1 > row) c1 = 0.f;
                __nv_bfloat162 lo;
                __nv_bfloat162 hi = split_pair(c0, c1, lo);
                *(__nv_bfloat162*)(smem + OKH + row * PQB + col * 2) = hi;
                *(__nv_bfloat162*)(smem + OKL + row * PQB + col * 2) = lo;
            }
    __syncthreads();

    if (tid < 128) {
        const __nv_bfloat16* ah_ = (const __nv_bfloat16*)(smem + OKH + tid * PQB);
        const __nv_bfloat16* al_ = (const __nv_bfloat16*)(smem + OKL + tid * PQB);
        const __nv_bfloat16* qh_ = (const __nv_bfloat16*)(smem + OQH + tid * PQB);
        const __nv_bfloat16* ql_ = (const __nv_bfloat16*)(smem + OQL + tid * PQB);
        const float* zf = (const float*)(smem + OZ);
        float s = 0.f;
        for (int j = 0; j < NF; j++)
            s += __bfloat162float(ah_[j]) + __bfloat162float(al_[j]);
        for (int j = 0; j < NF; j++)
            s += (__bfloat162float(qh_[j]) + __bfloat162float(ql_[j])) * zf[j];
        ((float*)(smem + ODEN))[tid] = s;
    }
    __syncthreads();

    float accO[2][4][4];
#pragma unroll
    for (int mt = 0; mt < 2; mt++)
#pragma unroll
        for (int nt = 0; nt < 4; nt++)
#pragma unroll
            for (int i = 0; i < 4; i++) accO[mt][nt][i] = 0.f;

    int bt_row = (lane & 7) + ((lane >> 3) & 1) * 8;
    int bt_nt = lane >> 4;

#pragma unroll
    for (int kt = 0; kt < 16; kt++) {
        int isA = (kt < 8);
        uint32_t abase = isA ? OKH : OQH;
        uint32_t abl = isA ? OKL : OQL;
        uint32_t bbase = isA ? OVH : OSH;
        uint32_t bbl = isA ? OVL : OSL;
        int kk = (kt & 7) * 16;
        uint32_t fah[2][4], fal[2][4];
#pragma unroll
        for (int mt = 0; mt < 2; mt++) {
            uint32_t addr = sm + abase + (wm * 32 + mt * 16 + a_row) * PQB +
                            (kk + a_koff) * 2;
            ldm_x4(fah[mt], addr);
            ldm_x4(fal[mt], addr + (abl - abase));
        }
        uint32_t fbh[4][2], fbl[4][2];
#pragma unroll
        for (int ntp = 0; ntp < 2; ntp++) {
            uint32_t addr = sm + bbase + (kk + bt_row) * PVB +
                            (wn * 32 + ntp * 16 + bt_nt * 8) * 2;
            uint32_t t4[4];
            ldm_x4t(t4, addr);
            fbh[2 * ntp][0] = t4[0]; fbh[2 * ntp][1] = t4[1];
            fbh[2 * ntp + 1][0] = t4[2]; fbh[2 * ntp + 1][1] = t4[3];
            ldm_x4t(t4, addr + (bbl - bbase));
            fbl[2 * ntp][0] = t4[0]; fbl[2 * ntp][1] = t4[1];
            fbl[2 * ntp + 1][0] = t4[2]; fbl[2 * ntp + 1][1] = t4[3];
        }
#pragma unroll
        for (int mt = 0; mt < 2; mt++)
#pragma unroll
            for (int nt = 0; nt < 4; nt++) {
                mma16816(accO[mt][nt], fah[mt], fbh[nt]);
                mma16816(accO[mt][nt], fal[mt], fbh[nt]);
                mma16816(accO[mt][nt], fah[mt], fbl[nt]);
            }
    }

    const float* den = (const float*)(smem + ODEN);
#pragma unroll
    for (int mt = 0; mt < 2; mt++)
#pragma unroll
        for (int nt = 0; nt < 4; nt++)
#pragma unroll
            for (int rh = 0; rh < 2; rh++) {
                int row = wm * 32 + mt * 16 + gid + rh * 8;
                int col = wn * 32 + nt * 8 + tig * 2;
                float inv = 1.0f / (den[row] + EPSV);
                float v0 = accO[mt][nt][2 * rh] * inv;
                float v1 = accO[mt][nt][2 * rh + 1] * inv;
                __nv_bfloat162 lo;
                __nv_bfloat162 hi = split_pair(v0, v1, lo);
                size_t go = (size_t)(b * TT + c * CC + row) * DM + h * HD + col;
                *(__nv_bfloat162*)(yh + go) = hi;
                *(__nv_bfloat162*)(yl + go) = lo;
            }
}

// ---------------- launcher ----------------------------------------------------
extern "C" void kernel_launch(void* const* d_in, const int* in_sizes, int n_in,
                              void* d_out, int out_size) {
    const float* x  = (const float*)d_in[0];
    const float* Wq = (const float*)d_in[1];
    const float* Wk = (const float*)d_in[2];
    const float* Wv = (const float*)d_in[3];
    const float* Wo = (const float*)d_in[4];
    const float* Wf = (const float*)d_in[5];
    float* out = (float*)d_out;

    float *pq, *pk, *pS, *pz;
    __nv_bfloat16 *pxh, *pxl, *pvh, *pvl, *pyh, *pyl, *pwh, *pwl;
    __nv_bfloat16 *pqph, *pqpl, *pkph, *pkpl;
    cudaGetSymbolAddress((void**)&pq,  g_q);
    cudaGetSymbolAddress((void**)&pk,  g_k);
    cudaGetSymbolAddress((void**)&pS,  g_S);
    cudaGetSymbolAddress((void**)&pz,  g_z);
    cudaGetSymbolAddress((void**)&pxh, g_xh);
    cudaGetSymbolAddress((void**)&pxl, g_xl);
    cudaGetSymbolAddress((void**)&pvh, g_vh);
    cudaGetSymbolAddress((void**)&pvl, g_vl);
    cudaGetSymbolAddress((void**)&pyh, g_yh);
    cudaGetSymbolAddress((void**)&pyl, g_yl);
    cudaGetSymbolAddress((void**)&pwh, g_wh);
    cudaGetSymbolAddress((void**)&pwl, g_wl);
    cudaGetSymbolAddress((void**)&pqph, g_qph);
    cudaGetSymbolAddress((void**)&pqpl, g_qpl);
    cudaGetSymbolAddress((void**)&pkph, g_kph);
    cudaGetSymbolAddress((void**)&pkpl, g_kpl);

    cudaFuncSetAttribute(gemm_big<0>, cudaFuncAttributeMaxDynamicSharedMemorySize, BSMEM);
    cudaFuncSetAttribute(gemm_big<1>, cudaFuncAttributeMaxDynamicSharedMemorySize, BSMEM);
    cudaFuncSetAttribute(feature_mma_kernel, cudaFuncAttributeMaxDynamicSharedMemorySize, FSMEM);
    cudaFuncSetAttribute(chunk_kv_mma, cudaFuncAttributeMaxDynamicSharedMemorySize, CSMEM);
    cudaFuncSetAttribute(attn_mma_kernel, cudaFuncAttributeMaxDynamicSharedMemorySize, ATTN_SMEM);

    // 1. split x
    split_kernel<<<2048, 256>>>(x, pxh, pxl, ROWS * DM / 4);
    // 2. transpose + split all 4 weights in one launch
    wsplit4_kernel<<<dim3(DM / 32, DM / 32, 4), 256>>>(Wq, Wk, Wv, Wo, pwh, pwl);

    // 3. fused QKV projection (N = 3072), full 3-pass everywhere
    gemm_big<1><<<dim3(12, ROWS / BGM), 512, BSMEM>>>(pxh, pxl, pwh, pwl,
                                                      pq, pk, pvh, pvl);

    // 4. feature map + attention
    feature_mma_kernel<<<dim3(BHT / 128, 2), 256, FSMEM>>>(pq, pk, Wf,
                                                           pqph, pqpl, pkph, pkpl);
    chunk_kv_mma<<<BB * HH * NCH, 256, CSMEM>>>(pkph, pkpl, pvh, pvl, pS, pz);
    prefix_kernel<<<dim3(BB * HH, 4), 256>>>(pS, pz);
    attn_mma_kernel<<<BB * HH * NCH, 256, ATTN_SMEM>>>(pqph, pqpl, pkph, pkpl,
                                                       pvh, pvl, pS, pz, pyh, pyl);

    // 5. output projection (N = 1024)
    gemm_big<0><<<dim3(4, ROWS / BGM), 512, BSMEM>>>(
        pyh, pyl, pwh + 3 * (size_t)DM * DM, pwl + 3 * (size_t)DM * DM,
        out, nullptr, nullptr, nullptr);
}